// round 10
// baseline (speedup 1.0000x reference)
#include <cuda_runtime.h>
#include <cuda_fp16.h>
#include <math.h>
#include <stdint.h>

#define BATCH 16
#define NPTS  16384
#define BNTOT (BATCH*NPTS)
#define NTILE (BNTOT/256)   // 1024 column tiles (fp32 gemm path)
#define HPT   8192          // hmma stats partials per channel

typedef unsigned long long ull;

// ---------------- packed f32x2 / fp16 helpers --------------------------------
__device__ __forceinline__ ull pack2(float lo, float hi) {
    ull r; asm("mov.b64 %0, {%1, %2};" : "=l"(r) : "f"(lo), "f"(hi)); return r;
}
__device__ __forceinline__ ull fma2(ull a, ull b, ull c) {
    ull d; asm("fma.rn.f32x2 %0, %1, %2, %3;" : "=l"(d) : "l"(a), "l"(b), "l"(c)); return d;
}
__device__ __forceinline__ void unpack2(ull v, float& lo, float& hi) {
    asm("mov.b64 {%0, %1}, %2;" : "=f"(lo), "=f"(hi) : "l"(v));
}
__device__ __forceinline__ uint32_t cvt_h2(float lo, float hi) {
    uint32_t r;
    asm("cvt.rn.satfinite.f16x2.f32 %0, %1, %2;" : "=r"(r) : "f"(hi), "f"(lo));
    return r;
}
__device__ __forceinline__ float lo_h2(uint32_t h) {
    __half2 hh = *reinterpret_cast<const __half2*>(&h);
    return __low2float(hh);
}
__device__ __forceinline__ float hi_h2(uint32_t h) {
    __half2 hh = *reinterpret_cast<const __half2*>(&h);
    return __high2float(hh);
}
// main term: fp32 accumulate
__device__ __forceinline__ void mma_f16(float d[4], const uint32_t a[4], const uint32_t b[2]) {
    asm volatile("mma.sync.aligned.m16n8k16.row.col.f32.f16.f16.f32 "
        "{%0,%1,%2,%3}, {%4,%5,%6,%7}, {%8,%9}, {%0,%1,%2,%3};"
        : "+f"(d[0]), "+f"(d[1]), "+f"(d[2]), "+f"(d[3])
        : "r"(a[0]), "r"(a[1]), "r"(a[2]), "r"(a[3]), "r"(b[0]), "r"(b[1]));
}
// correction terms: fp16 accumulate (2x rate on legacy tensor path)
__device__ __forceinline__ void mma_f16acc(uint32_t d[2], const uint32_t a[4], const uint32_t b[2]) {
    asm volatile("mma.sync.aligned.m16n8k16.row.col.f16.f16.f16.f16 "
        "{%0,%1}, {%2,%3,%4,%5}, {%6,%7}, {%0,%1};"
        : "+r"(d[0]), "+r"(d[1])
        : "r"(a[0]), "r"(a[1]), "r"(a[2]), "r"(a[3]), "r"(b[0]), "r"(b[1]));
}
// canonical A-fragment load: 16x16 f16 tile, rows contiguous in smem
__device__ __forceinline__ void ldsm_x4(uint32_t r[4], const uint32_t* p) {
    uint32_t a = (uint32_t)__cvta_generic_to_shared(p);
    asm volatile("ldmatrix.sync.aligned.m8n8.x4.shared.b16 {%0,%1,%2,%3}, [%4];"
        : "=r"(r[0]), "=r"(r[1]), "=r"(r[2]), "=r"(r[3]) : "r"(a));
}

// ---------------- scratch (device globals) ----------------------------------
__device__ float g_y1[(size_t)BATCH*64*NPTS];
__device__ float g_y2[(size_t)BATCH*128*NPTS];
__device__ float g_y3[(size_t)BATCH*32*NPTS];
__device__ float g_y4[(size_t)BATCH*512*NPTS];
__device__ float g_y5[(size_t)BATCH*256*NPTS];
__device__ float g_y6[(size_t)BATCH*128*NPTS];
__device__ float g_bsum[(size_t)64*NTILE];      // L1 fused stats [c][tile]
__device__ float g_bsq [(size_t)64*NTILE];
__device__ float g_hsum[(size_t)512*HPT];       // hmma fused stats [c][tile*4+warpN]
__device__ float g_hsq [(size_t)512*HPT];
__device__ float g_scale[6][512];
__device__ float g_shift[6][512];
__device__ float g_v[BATCH*32];
__device__ float g_bias4[BATCH*512];

// =================== HMMA fp16 3-term-split GEMM (layers 2-6) ================
// Per 32-channel chunk: A = [wh(16w) | wl(16w)], B = [xh(16r) | xl(16r)].
// Main term wh*xh -> fp32 accumulators; corrections wh*xl + wl*xh -> fp16
// accumulators (2x-rate mma), added to the fp32 result in the epilogue.
#define A_STR  36               // 32 data words + 4 pad
#define B_STR  136              // 128 data words + 8 pad
#define B0_W   2304             // A region = 64*36 words
#define SBUF_W 6656             // + B region 32*136 = 4352 words (26.6 KB/buf)

__global__ void __launch_bounds__(256, 2)
hmma_gemm_kernel(const float* __restrict__ W, int wstride,
                 const float* __restrict__ bias, int biasPerBatch,
                 const float* __restrict__ X, int Ci, int inLayer,
                 float* __restrict__ Y, int Co)
{
    extern __shared__ uint32_t sm[];
    const int t    = threadIdx.x;
    const int lane = t & 31, wid = t >> 5;
    const int warpM = wid & 1, warpN = wid >> 1;   // 2 x 4 warps, warp tile 32x32
    const int l4 = lane >> 2, q = lane & 3;
    const int b   = blockIdx.y >> 7;
    const int n0  = (blockIdx.y & 127) * 128;
    const int co0 = blockIdx.x * 64;

    const float* __restrict__ scv = g_scale[inLayer];
    const float* __restrict__ shv = g_shift[inLayer];
    const int nChunks = Ci >> 5;

    float    acc [2][4][4];    // main term (fp32)
    uint32_t accL[2][4][2];    // corrections (f16x2)
#pragma unroll
    for (int mt = 0; mt < 2; mt++)
#pragma unroll
        for (int nt = 0; nt < 4; nt++) {
#pragma unroll
            for (int j = 0; j < 4; j++) acc[mt][nt][j] = 0.f;
            accL[mt][nt][0] = 0u; accL[mt][nt][1] = 0u;
        }

    // register staging for the in-flight chunk
    float4 aw[2];           // weights
    float4 bx0[2], bx1[2];  // activations (channel pair)

    auto ldg_chunk = [&](int ci0) {
#pragma unroll
        for (int i = 0; i < 2; i++) {
            int slot = i*256 + t;
            int co = slot >> 3, f4 = slot & 7;
            int cog = co0 + co;
            aw[i] = (cog < Co) ? *(const float4*)&W[(size_t)cog*wstride + ci0 + f4*4]
                               : make_float4(0.f, 0.f, 0.f, 0.f);
        }
#pragma unroll
        for (int i = 0; i < 2; i++) {
            int slot = i*256 + t;
            int kp = slot >> 5, f4 = slot & 31;
            int c0 = ci0 + kp*2;
            bx0[i] = *(const float4*)&X[((size_t)b*Ci + c0  )*NPTS + n0 + f4*4];
            bx1[i] = *(const float4*)&X[((size_t)b*Ci + c0+1)*NPTS + n0 + f4*4];
        }
    };

    auto sts_chunk = [&](int bufW, int ci0) {
        // A: [wh | wl]
#pragma unroll
        for (int i = 0; i < 2; i++) {
            int slot = i*256 + t;
            int co = slot >> 3, f4 = slot & 7;
            float4 w = aw[i];
            uint32_t h0 = cvt_h2(w.x, w.y);
            uint32_t h1 = cvt_h2(w.z, w.w);
            uint32_t l0 = cvt_h2(w.x - lo_h2(h0), w.y - hi_h2(h0));
            uint32_t l1 = cvt_h2(w.z - lo_h2(h1), w.w - hi_h2(h1));
            int wi = bufW + co*A_STR + f4*2;
            *(uint2*)&sm[wi]      = make_uint2(h0, h1);   // wh
            *(uint2*)&sm[wi + 16] = make_uint2(l0, l1);   // wl
        }
        // B: [xh | xl], BN+ReLU fused
#pragma unroll
        for (int i = 0; i < 2; i++) {
            int slot = i*256 + t;
            int kp = slot >> 5, f4 = slot & 31;
            int c0 = ci0 + kp*2;
            float s0 = scv[c0],   h0s = shv[c0];
            float s1 = scv[c0+1], h1s = shv[c0+1];
            float x0[4] = {bx0[i].x, bx0[i].y, bx0[i].z, bx0[i].w};
            float x1[4] = {bx1[i].x, bx1[i].y, bx1[i].z, bx1[i].w};
            uint32_t hw[4], lw[4];
#pragma unroll
            for (int j = 0; j < 4; j++) {
                float a0 = fmaxf(fmaf(x0[j], s0, h0s), 0.f);
                float a1 = fmaxf(fmaf(x1[j], s1, h1s), 0.f);
                uint32_t h = cvt_h2(a0, a1);
                hw[j] = h;
                lw[j] = cvt_h2(a0 - lo_h2(h), a1 - hi_h2(h));
            }
            int wi = bufW + B0_W + kp*B_STR + f4*4;
            *(uint4*)&sm[wi]            = make_uint4(hw[0], hw[1], hw[2], hw[3]); // xh
            *(uint4*)&sm[wi + 16*B_STR] = make_uint4(lw[0], lw[1], lw[2], lw[3]); // xl
        }
    };

    ldg_chunk(0);   // prologue

    // ldmatrix addressing (constant per thread)
    const int lrow = lane & 15;
    const int lkw  = (lane >> 4) * 4;

    for (int c = 0; c < nChunks; c++) {
        const int bufW = (c & 1) * SBUF_W;
        sts_chunk(bufW, c << 5);
        __syncthreads();                         // STS(c) visible to all warps
        if (c + 1 < nChunks) ldg_chunk((c+1) << 5);   // latency hidden by compute

        const uint32_t* Aw = sm + bufW;
        const uint32_t* Bx = sm + bufW + B0_W;

#pragma unroll
        for (int kg = 0; kg < 2; kg++) {         // k16 group within the chunk
            uint32_t ah[2][4], al[2][4];
#pragma unroll
            for (int mt = 0; mt < 2; mt++) {
                const uint32_t* base =
                    Aw + (warpM*32 + mt*16 + lrow) * A_STR + kg*8 + lkw;
                ldsm_x4(ah[mt], base);           // wh fragment
                ldsm_x4(al[mt], base + 16);      // wl fragment
            }
            uint32_t bh[4][2], bl[4][2];
#pragma unroll
            for (int nt = 0; nt < 4; nt++) {
                int base = (kg*8 + q) * B_STR + warpN*32 + nt*8 + l4;
                bh[nt][0] = Bx[base];             bh[nt][1] = Bx[base + 4*B_STR];
                bl[nt][0] = Bx[base + 16*B_STR];  bl[nt][1] = Bx[base + 20*B_STR];
            }
#pragma unroll
            for (int mt = 0; mt < 2; mt++)
#pragma unroll
                for (int nt = 0; nt < 4; nt++) {
                    mma_f16(acc[mt][nt], ah[mt], bh[nt]);         // main, fp32 acc
                    mma_f16acc(accL[mt][nt], ah[mt], bl[nt]);     // corr, fp16 acc
                    mma_f16acc(accL[mt][nt], al[mt], bh[nt]);     // corr, fp16 acc
                }
        }
    }

    // ---- epilogue: combine main + corrections, store Y + fused stats ----
    const int tileIdx = blockIdx.y * 4 + warpN;
#pragma unroll
    for (int mt = 0; mt < 2; mt++) {
        int row0 = co0 + warpM*32 + mt*16 + l4;
        int row1 = row0 + 8;
        float bs0 = 0.f, bs1 = 0.f;
        if (row0 < Co) bs0 = biasPerBatch ? bias[(size_t)b*Co + row0] : bias[row0];
        if (row1 < Co) bs1 = biasPerBatch ? bias[(size_t)b*Co + row1] : bias[row1];
        float s0 = 0.f, q0 = 0.f, s1 = 0.f, q1 = 0.f;
#pragma unroll
        for (int nt = 0; nt < 4; nt++) {
            int col = n0 + warpN*32 + nt*8 + q*2;
            float o0 = acc[mt][nt][0] + lo_h2(accL[mt][nt][0]) + bs0;
            float o1 = acc[mt][nt][1] + hi_h2(accL[mt][nt][0]) + bs0;
            float o2 = acc[mt][nt][2] + lo_h2(accL[mt][nt][1]) + bs1;
            float o3 = acc[mt][nt][3] + hi_h2(accL[mt][nt][1]) + bs1;
            s0 += o0 + o1;  q0 = fmaf(o0, o0, q0); q0 = fmaf(o1, o1, q0);
            s1 += o2 + o3;  q1 = fmaf(o2, o2, q1); q1 = fmaf(o3, o3, q1);
            if (row0 < Co)
                *(float2*)&Y[((size_t)b*Co + row0)*NPTS + col] = make_float2(o0, o1);
            if (row1 < Co)
                *(float2*)&Y[((size_t)b*Co + row1)*NPTS + col] = make_float2(o2, o3);
        }
        s0 += __shfl_xor_sync(0xffffffffu, s0, 1);  s0 += __shfl_xor_sync(0xffffffffu, s0, 2);
        q0 += __shfl_xor_sync(0xffffffffu, q0, 1);  q0 += __shfl_xor_sync(0xffffffffu, q0, 2);
        s1 += __shfl_xor_sync(0xffffffffu, s1, 1);  s1 += __shfl_xor_sync(0xffffffffu, s1, 2);
        q1 += __shfl_xor_sync(0xffffffffu, q1, 1);  q1 += __shfl_xor_sync(0xffffffffu, q1, 2);
        if (q == 0) {
            if (row0 < Co) {
                g_hsum[(size_t)row0*HPT + tileIdx] = s0;
                g_hsq [(size_t)row0*HPT + tileIdx] = q0;
            }
            if (row1 < Co) {
                g_hsum[(size_t)row1*HPT + tileIdx] = s1;
                g_hsq [(size_t)row1*HPT + tileIdx] = q1;
            }
        }
    }
}

// ---------------- finalize3: reduce HPT partials -> BN scale/shift ----------
__global__ void __launch_bounds__(256)
finalize3_kernel(const float* __restrict__ gamma,
                 const float* __restrict__ beta, int layer)
{
    const int c = blockIdx.x;
    const int t = threadIdx.x;
    float s = 0.f, q = 0.f;
#pragma unroll
    for (int i = 0; i < HPT/256; i++) {
        s += g_hsum[(size_t)c * HPT + i*256 + t];
        q += g_hsq [(size_t)c * HPT + i*256 + t];
    }
    __shared__ float ss[256], sq[256];
    ss[t] = s; sq[t] = q;
    __syncthreads();
    for (int st = 128; st > 0; st >>= 1) {
        if (t < st) { ss[t] += ss[t + st]; sq[t] += sq[t + st]; }
        __syncthreads();
    }
    if (t == 0) {
        float m   = ss[0] * (1.0f / BNTOT);
        float var = sq[0] * (1.0f / BNTOT) - m * m;
        float rstd = rsqrtf(var + 1e-5f);
        float scl  = gamma[c] * rstd;
        g_scale[layer][c] = scl;
        g_shift[layer][c] = fmaf(-m, scl, beta[c]);
    }
}

// =================== fp32 FFMA2 GEMM (layer 1 only) ==========================
__global__ void __launch_bounds__(256, 2)
gemm_kernel(const float* __restrict__ W, int wstride,
            const float* __restrict__ bias,
            const float* __restrict__ X, int Ci,
            float* __restrict__ Y, int Co)
{
    __shared__ __align__(16) ull   As2[16][65];
    __shared__ __align__(16) float Xs[16][256];

    const int t  = threadIdx.x;
    const int tn = t & 15;
    const int r  = t >> 4;
    const int tilesPerBatch = NPTS / 256;
    const int b   = blockIdx.y / tilesPerBatch;
    const int n0  = (blockIdx.y % tilesPerBatch) * 256;
    const int co0 = blockIdx.x * 64;

    ull acc2[4][8];
#pragma unroll
    for (int j = 0; j < 4; j++)
#pragma unroll
        for (int qq = 0; qq < 8; qq++) acc2[j][qq] = 0ull;

    const int nChunks = (Ci + 15) >> 4;
    float  wreg[4];
    float4 xreg[4];

    {
#pragma unroll
        for (int i = 0; i < 4; i++) {
            int lin = i*256 + t;
            int k = lin & 15, co = lin >> 4;
            int ci = k, cog = co0 + co;
            wreg[i] = (ci < Ci && cog < Co) ? W[(size_t)cog * wstride + ci] : 0.f;
        }
#pragma unroll
        for (int i = 0; i < 4; i++) {
            int fidx = i*256 + t;
            int k  = fidx >> 6;
            int n4 = fidx & 63;
            xreg[i] = (k < Ci) ? *(const float4*)&X[((size_t)b * Ci + k) * NPTS + n0 + n4*4]
                               : make_float4(0.f,0.f,0.f,0.f);
        }
    }

    for (int c = 0; c < nChunks; c++) {
        const int k0 = c << 4;
        if (c > 0) __syncthreads();
#pragma unroll
        for (int i = 0; i < 4; i++) {
            int lin = i*256 + t;
            int k = lin & 15, co = lin >> 4;
            float w = wreg[i];
            As2[k][co] = pack2(w, w);
        }
#pragma unroll
        for (int i = 0; i < 4; i++) {
            int fidx = i*256 + t;
            int k  = fidx >> 6;
            int n4 = fidx & 63;
            *(float4*)&Xs[k][n4*4] = xreg[i];
        }
        __syncthreads();

        if (c + 1 < nChunks) {
            const int k0n = k0 + 16;
#pragma unroll
            for (int i = 0; i < 4; i++) {
                int lin = i*256 + t;
                int k = lin & 15, co = lin >> 4;
                int ci = k0n + k, cog = co0 + co;
                wreg[i] = (ci < Ci && cog < Co) ? W[(size_t)cog * wstride + ci] : 0.f;
            }
#pragma unroll
            for (int i = 0; i < 4; i++) {
                int fidx = i*256 + t;
                int k  = fidx >> 6;
                int n4 = fidx & 63;
                int ci = k0n + k;
                xreg[i] = (ci < Ci) ? *(const float4*)&X[((size_t)b * Ci + ci) * NPTS + n0 + n4*4]
                                    : make_float4(0.f,0.f,0.f,0.f);
            }
        }

#pragma unroll
        for (int kk = 0; kk < 16; kk++) {
            ull a0 = As2[kk][r*4 + 0];
            ull a1 = As2[kk][r*4 + 1];
            ull a2 = As2[kk][r*4 + 2];
            ull a3 = As2[kk][r*4 + 3];
#pragma unroll
            for (int g = 0; g < 4; g++) {
                ulonglong2 xv = *(const ulonglong2*)&Xs[kk][g*64 + tn*4];
                acc2[0][g*2+0] = fma2(a0, xv.x, acc2[0][g*2+0]);
                acc2[0][g*2+1] = fma2(a0, xv.y, acc2[0][g*2+1]);
                acc2[1][g*2+0] = fma2(a1, xv.x, acc2[1][g*2+0]);
                acc2[1][g*2+1] = fma2(a1, xv.y, acc2[1][g*2+1]);
                acc2[2][g*2+0] = fma2(a2, xv.x, acc2[2][g*2+0]);
                acc2[2][g*2+1] = fma2(a2, xv.y, acc2[2][g*2+1]);
                acc2[3][g*2+0] = fma2(a3, xv.x, acc2[3][g*2+0]);
                acc2[3][g*2+1] = fma2(a3, xv.y, acc2[3][g*2+1]);
            }
        }
    }

    const int tile = blockIdx.y;
#pragma unroll
    for (int j = 0; j < 4; j++) {
        int cog = co0 + r*4 + j;
        bool valid = (cog < Co);
        float bs = valid ? bias[cog] : 0.f;
        float s = 0.f, q = 0.f;
        float* yr = valid ? &Y[((size_t)b * Co + cog) * NPTS + n0] : (float*)0;
#pragma unroll
        for (int g = 0; g < 4; g++) {
            float4 o;
            unpack2(acc2[j][g*2+0], o.x, o.y);
            unpack2(acc2[j][g*2+1], o.z, o.w);
            o.x += bs; o.y += bs; o.z += bs; o.w += bs;
            s += (o.x + o.y) + (o.z + o.w);
            q = fmaf(o.x, o.x, q); q = fmaf(o.y, o.y, q);
            q = fmaf(o.z, o.z, q); q = fmaf(o.w, o.w, q);
            if (valid) *(float4*)&yr[g*64 + tn*4] = o;
        }
#pragma unroll
        for (int off = 8; off; off >>= 1) {
            s += __shfl_down_sync(0xffffffffu, s, off, 16);
            q += __shfl_down_sync(0xffffffffu, q, off, 16);
        }
        if (tn == 0 && valid) {
            g_bsum[(size_t)cog * NTILE + tile] = s;
            g_bsq [(size_t)cog * NTILE + tile] = q;
        }
    }
}

// ---------------- finalize for L1 ([c][NTILE]) -------------------------------
__global__ void __launch_bounds__(256)
finalize_kernel(const float* __restrict__ gamma,
                const float* __restrict__ beta, int layer)
{
    const int c = blockIdx.x;
    const int t = threadIdx.x;
    float s = 0.f, q = 0.f;
#pragma unroll
    for (int i = 0; i < NTILE/256; i++) {
        s += g_bsum[(size_t)c * NTILE + i*256 + t];
        q += g_bsq [(size_t)c * NTILE + i*256 + t];
    }
    __shared__ float ss[256], sq[256];
    ss[t] = s; sq[t] = q;
    __syncthreads();
    for (int st = 128; st > 0; st >>= 1) {
        if (t < st) { ss[t] += ss[t + st]; sq[t] += sq[t + st]; }
        __syncthreads();
    }
    if (t == 0) {
        float m   = ss[0] * (1.0f / BNTOT);
        float var = sq[0] * (1.0f / BNTOT) - m * m;
        float rstd = rsqrtf(var + 1e-5f);
        float scl  = gamma[c] * rstd;
        g_scale[layer][c] = scl;
        g_shift[layer][c] = fmaf(-m, scl, beta[c]);
    }
}

// ---------------- dedicated L7: 128 -> 3, tanh ------------------------------
__global__ void __launch_bounds__(256)
conv7_kernel(const float* __restrict__ w7, const float* __restrict__ b7,
             const float* __restrict__ Y6, float* __restrict__ out)
{
    __shared__ float sw0[128], sw1[128], sw2[128], ssc[128], ssh[128];
    const int t = threadIdx.x;
    if (t < 128) {
        sw0[t] = w7[t]; sw1[t] = w7[128 + t]; sw2[t] = w7[256 + t];
        ssc[t] = g_scale[5][t]; ssh[t] = g_shift[5][t];
    }
    __syncthreads();

    const int idx = blockIdx.x * 256 + t;        // 65536 threads, 4 pts each
    const int b = idx >> 12;
    const int n = (idx & 4095) * 4;

    float4 a0 = make_float4(0.f,0.f,0.f,0.f);
    float4 a1 = a0, a2 = a0;
#pragma unroll 4
    for (int c = 0; c < 128; c++) {
        float4 v = *(const float4*)&Y6[((size_t)b*128 + c)*NPTS + n];
        float s = ssc[c], h = ssh[c];
        v.x = fmaxf(fmaf(v.x, s, h), 0.f);
        v.y = fmaxf(fmaf(v.y, s, h), 0.f);
        v.z = fmaxf(fmaf(v.z, s, h), 0.f);
        v.w = fmaxf(fmaf(v.w, s, h), 0.f);
        float w0 = sw0[c], w1 = sw1[c], w2 = sw2[c];
        a0.x = fmaf(w0, v.x, a0.x); a0.y = fmaf(w0, v.y, a0.y);
        a0.z = fmaf(w0, v.z, a0.z); a0.w = fmaf(w0, v.w, a0.w);
        a1.x = fmaf(w1, v.x, a1.x); a1.y = fmaf(w1, v.y, a1.y);
        a1.z = fmaf(w1, v.z, a1.z); a1.w = fmaf(w1, v.w, a1.w);
        a2.x = fmaf(w2, v.x, a2.x); a2.y = fmaf(w2, v.y, a2.y);
        a2.z = fmaf(w2, v.z, a2.z); a2.w = fmaf(w2, v.w, a2.w);
    }
    float b0 = b7[0], b1 = b7[1], b2 = b7[2];
    float4 o0 = make_float4(tanhf(a0.x+b0), tanhf(a0.y+b0), tanhf(a0.z+b0), tanhf(a0.w+b0));
    float4 o1 = make_float4(tanhf(a1.x+b1), tanhf(a1.y+b1), tanhf(a1.z+b1), tanhf(a1.w+b1));
    float4 o2 = make_float4(tanhf(a2.x+b2), tanhf(a2.y+b2), tanhf(a2.z+b2), tanhf(a2.w+b2));
    *(float4*)&out[((size_t)b*3 + 0)*NPTS + n] = o0;
    *(float4*)&out[((size_t)b*3 + 1)*NPTS + n] = o1;
    *(float4*)&out[((size_t)b*3 + 2)*NPTS + n] = o2;
}

// ---------------- SoftPool with smem row cache -------------------------------
__global__ void __launch_bounds__(256)
softpool_kernel(const float* __restrict__ w9, const float* __restrict__ b9)
{
    extern __shared__ float cache[];   // 16384 floats (64 KB)
    const int b = blockIdx.x >> 5;
    const int k = blockIdx.x & 31;
    const int t = threadIdx.x;

    __shared__ float sVal[256];
    __shared__ int   sIdx[256];
    __shared__ int   selIdx[16];

    const float sc = g_scale[2][k], sh = g_shift[2][k];
    const float* __restrict__ row = &g_y3[((size_t)b * 32 + k) * NPTS];

    for (int n = t; n < NPTS; n += 256) cache[n] = fmaf(row[n], sc, sh);
    __syncthreads();

    float lastV = -3.402823466e38f;
    int   lastI = -1;

    for (int p = 0; p < 16; p++) {
        float bv = 3.402823466e38f;
        int   bi = NPTS;
        for (int n = t; n < NPTS; n += 256) {
            float val = cache[n];
            bool elig = (val > lastV) || (val == lastV && n > lastI);
            if (elig && (val < bv || (val == bv && n < bi))) { bv = val; bi = n; }
        }
        sVal[t] = bv; sIdx[t] = bi;
        __syncthreads();
        for (int st = 128; st > 0; st >>= 1) {
            if (t < st) {
                float ov = sVal[t + st]; int oi = sIdx[t + st];
                if (ov < sVal[t] || (ov == sVal[t] && oi < sIdx[t])) { sVal[t] = ov; sIdx[t] = oi; }
            }
            __syncthreads();
        }
        lastV = sVal[0]; lastI = sIdx[0];
        if (t == 0) selIdx[p] = sIdx[0];
        __syncthreads();
    }

    float part = 0.f;
    for (int i = t; i < 512; i += 256) {
        int c = i >> 4, p = i & 15;
        int n = selIdx[p];
        float val = fmaf(g_y3[((size_t)b * 32 + c) * NPTS + n], g_scale[2][c], g_shift[2][c]);
        part = fmaf(w9[c * 16 + p], val, part);
    }
    sVal[t] = part;
    __syncthreads();
    for (int st = 128; st > 0; st >>= 1) {
        if (t < st) sVal[t] += sVal[t + st];
        __syncthreads();
    }
    if (t == 0) g_v[b * 32 + k] = sVal[0] + b9[0];
}

// ---------------- fold glob into conv4 bias ---------------------------------
__global__ void bias4_kernel(const float* __restrict__ w4, const float* __restrict__ b4)
{
    int idx = blockIdx.x * 256 + threadIdx.x;
    if (idx >= BATCH * 512) return;
    int b = idx >> 9, co = idx & 511;
    float s = b4[co];
#pragma unroll
    for (int k = 0; k < 32; k++) s = fmaf(w4[co * 96 + k], g_v[b * 32 + k], s);
    g_bias4[idx] = s;
}

// ---------------------------------------------------------------------------
extern "C" void kernel_launch(void* const* d_in, const int* in_sizes, int n_in,
                              void* d_out, int out_size)
{
    const float* x   = (const float*)d_in[0];
    const float* w1  = (const float*)d_in[1];  const float* b1  = (const float*)d_in[2];
    const float* g1  = (const float*)d_in[3];  const float* be1 = (const float*)d_in[4];
    const float* w2  = (const float*)d_in[5];  const float* b2  = (const float*)d_in[6];
    const float* g2  = (const float*)d_in[7];  const float* be2 = (const float*)d_in[8];
    const float* w3  = (const float*)d_in[9];  const float* b3  = (const float*)d_in[10];
    const float* g3  = (const float*)d_in[11]; const float* be3 = (const float*)d_in[12];
    const float* w9  = (const float*)d_in[13]; const float* b9  = (const float*)d_in[14];
    const float* w4  = (const float*)d_in[15]; const float* b4  = (const float*)d_in[16];
    const float* g4  = (const float*)d_in[17]; const float* be4 = (const float*)d_in[18];
    const float* w5  = (const float*)d_in[19]; const float* b5  = (const float*)d_in[20];
    const float* g5  = (const float*)d_in[21]; const float* be5 = (const float*)d_in[22];
    const float* w6  = (const float*)d_in[23]; const float* b6  = (const float*)d_in[24];
    const float* g6  = (const float*)d_in[25]; const float* be6 = (const float*)d_in[26];
    const float* w7  = (const float*)d_in[27]; const float* b7  = (const float*)d_in[28];

    float *y1, *y2, *y3, *y4, *y5, *y6, *bias4p;
    cudaGetSymbolAddress((void**)&y1, g_y1);
    cudaGetSymbolAddress((void**)&y2, g_y2);
    cudaGetSymbolAddress((void**)&y3, g_y3);
    cudaGetSymbolAddress((void**)&y4, g_y4);
    cudaGetSymbolAddress((void**)&y5, g_y5);
    cudaGetSymbolAddress((void**)&y6, g_y6);
    cudaGetSymbolAddress((void**)&bias4p, g_bias4);

    const int SMEM = 2 * SBUF_W * 4;   // 53248 B
    cudaFuncSetAttribute(hmma_gemm_kernel, cudaFuncAttributeMaxDynamicSharedMemorySize, SMEM);
    const int SPSM = NPTS * 4;         // 65536 B
    cudaFuncSetAttribute(softpool_kernel, cudaFuncAttributeMaxDynamicSharedMemorySize, SPSM);

    const dim3 blk(256);

    // L1: 4 -> 64 (fp32, fused stats)
    gemm_kernel<<<dim3(1, NTILE), blk>>>(w1, 4, b1, x, 4, y1, 64);
    finalize_kernel<<<64, 256>>>(g1, be1, 0);

    // L2: 64 -> 128 (HMMA, fused stats)
    hmma_gemm_kernel<<<dim3(2, 2048), blk, SMEM>>>(w2, 64, b2, 0, y1, 64, 0, y2, 128);
    finalize3_kernel<<<128, 256>>>(g2, be2, 1);

    // L3: 128 -> 32 (HMMA)
    hmma_gemm_kernel<<<dim3(1, 2048), blk, SMEM>>>(w3, 128, b3, 0, y2, 128, 1, y3, 32);
    finalize3_kernel<<<32, 256>>>(g3, be3, 2);

    // SoftPool + fold glob into conv4 bias
    softpool_kernel<<<512, 256, SPSM>>>(w9, b9);
    bias4_kernel<<<32, 256>>>(w4, b4);

    // L4: 64 -> 512 on h1 (HMMA, per-batch bias, glob folded, weight rows offset 32)
    hmma_gemm_kernel<<<dim3(8, 2048), blk, SMEM>>>(w4 + 32, 96, bias4p, 1, y1, 64, 0, y4, 512);
    finalize3_kernel<<<512, 256>>>(g4, be4, 3);

    // L5: 512 -> 256 (HMMA)
    hmma_gemm_kernel<<<dim3(4, 2048), blk, SMEM>>>(w5, 512, b5, 0, y4, 512, 3, y5, 256);
    finalize3_kernel<<<256, 256>>>(g5, be5, 4);

    // L6: 256 -> 128 (HMMA)
    hmma_gemm_kernel<<<dim3(2, 2048), blk, SMEM>>>(w6, 256, b6, 0, y5, 256, 4, y6, 128);
    finalize3_kernel<<<128, 256>>>(g6, be6, 5);

    // L7: 128 -> 3, tanh, dedicated kernel, straight to output
    conv7_kernel<<<BNTOT/4/256, blk>>>(w7, b7, y6, (float*)d_out);
}

// round 12
// speedup vs baseline: 1.1109x; 1.1109x over previous
#include <cuda_runtime.h>
#include <cuda_fp16.h>
#include <math.h>
#include <stdint.h>

#define BATCH 16
#define NPTS  16384
#define BNTOT (BATCH*NPTS)
#define NTILE (BNTOT/256)   // 1024 column tiles (fp32 gemm path)
#define HPT   8192          // hmma stats partials per channel

typedef unsigned long long ull;

// ---------------- packed f32x2 / fp16 helpers --------------------------------
__device__ __forceinline__ ull pack2(float lo, float hi) {
    ull r; asm("mov.b64 %0, {%1, %2};" : "=l"(r) : "f"(lo), "f"(hi)); return r;
}
__device__ __forceinline__ ull fma2(ull a, ull b, ull c) {
    ull d; asm("fma.rn.f32x2 %0, %1, %2, %3;" : "=l"(d) : "l"(a), "l"(b), "l"(c)); return d;
}
__device__ __forceinline__ void unpack2(ull v, float& lo, float& hi) {
    asm("mov.b64 {%0, %1}, %2;" : "=f"(lo), "=f"(hi) : "l"(v));
}
__device__ __forceinline__ uint32_t cvt_h2(float lo, float hi) {
    uint32_t r;
    asm("cvt.rn.satfinite.f16x2.f32 %0, %1, %2;" : "=r"(r) : "f"(hi), "f"(lo));
    return r;
}
__device__ __forceinline__ float lo_h2(uint32_t h) {
    __half2 hh = *reinterpret_cast<const __half2*>(&h);
    return __low2float(hh);
}
__device__ __forceinline__ float hi_h2(uint32_t h) {
    __half2 hh = *reinterpret_cast<const __half2*>(&h);
    return __high2float(hh);
}
__device__ __forceinline__ void mma_f16(float d[4], const uint32_t a[4], const uint32_t b[2]) {
    asm volatile("mma.sync.aligned.m16n8k16.row.col.f32.f16.f16.f32 "
        "{%0,%1,%2,%3}, {%4,%5,%6,%7}, {%8,%9}, {%0,%1,%2,%3};"
        : "+f"(d[0]), "+f"(d[1]), "+f"(d[2]), "+f"(d[3])
        : "r"(a[0]), "r"(a[1]), "r"(a[2]), "r"(a[3]), "r"(b[0]), "r"(b[1]));
}
// canonical A-fragment load: 16x16 f16 tile, rows contiguous in smem
__device__ __forceinline__ void ldsm_x4(uint32_t r[4], const uint32_t* p) {
    uint32_t a = (uint32_t)__cvta_generic_to_shared(p);
    asm volatile("ldmatrix.sync.aligned.m8n8.x4.shared.b16 {%0,%1,%2,%3}, [%4];"
        : "=r"(r[0]), "=r"(r[1]), "=r"(r[2]), "=r"(r[3]) : "r"(a));
}

// ---------------- scratch (device globals) ----------------------------------
__device__ float g_y1[(size_t)BATCH*64*NPTS];
__device__ float g_y2[(size_t)BATCH*128*NPTS];
__device__ float g_y3[(size_t)BATCH*32*NPTS];
__device__ float g_y4[(size_t)BATCH*512*NPTS];
__device__ float g_y5[(size_t)BATCH*256*NPTS];
__device__ float g_y6[(size_t)BATCH*128*NPTS];
__device__ float g_bsum[(size_t)64*NTILE];      // L1 fused stats [c][tile]
__device__ float g_bsq [(size_t)64*NTILE];
__device__ float g_hsum[(size_t)512*HPT];       // hmma fused stats [c][tile*4+warpN]
__device__ float g_hsq [(size_t)512*HPT];
__device__ float g_scale[6][512];
__device__ float g_shift[6][512];
__device__ float g_v[BATCH*32];
__device__ float g_bias4[BATCH*512];

// =================== HMMA fp16 split GEMM (layers 2-6) =======================
// Per 32-channel chunk: A = [wh(16w) | wl(16w)], B = [xh(16r) | xl(16r)].
// SPLIT3=true : D = wh*xh + wh*xl + wl*xh  (48 MMA/chunk, ~2e-6 accuracy)
//               -- used for layers feeding the softpool argsort (L2,L3) and L6.
// SPLIT3=false: D = wh*xh + wh*xl          (32 MMA/chunk, ~2.8e-4/layer from
//               one-time weight rounding) -- used post-softpool (L4,L5), where
//               the computation is smooth (no discrete selection downstream).
#define A_STR  36               // 32 data words + 4 pad
#define B_STR  136              // 128 data words + 8 pad
#define B0_W   2304             // A region = 64*36 words
#define SBUF_W 6656             // + B region 32*136 = 4352 words (26.6 KB/buf)

template<bool SPLIT3>
__global__ void __launch_bounds__(256, 2)
hmma_gemm_kernel(const float* __restrict__ W, int wstride,
                 const float* __restrict__ bias, int biasPerBatch,
                 const float* __restrict__ X, int Ci, int inLayer,
                 float* __restrict__ Y, int Co)
{
    extern __shared__ uint32_t sm[];
    const int t    = threadIdx.x;
    const int lane = t & 31, wid = t >> 5;
    const int warpM = wid & 1, warpN = wid >> 1;   // 2 x 4 warps, warp tile 32x32
    const int l4 = lane >> 2, q = lane & 3;
    const int b   = blockIdx.y >> 7;
    const int n0  = (blockIdx.y & 127) * 128;
    const int co0 = blockIdx.x * 64;

    const float* __restrict__ scv = g_scale[inLayer];
    const float* __restrict__ shv = g_shift[inLayer];
    const int nChunks = Ci >> 5;

    float acc[2][4][4];
#pragma unroll
    for (int mt = 0; mt < 2; mt++)
#pragma unroll
        for (int nt = 0; nt < 4; nt++)
#pragma unroll
            for (int j = 0; j < 4; j++) acc[mt][nt][j] = 0.f;

    // register staging for the in-flight chunk
    float4 aw[2];           // weights
    float4 bx0[2], bx1[2];  // activations (channel pair)

    auto ldg_chunk = [&](int ci0) {
#pragma unroll
        for (int i = 0; i < 2; i++) {
            int slot = i*256 + t;
            int co = slot >> 3, f4 = slot & 7;
            int cog = co0 + co;
            aw[i] = (cog < Co) ? *(const float4*)&W[(size_t)cog*wstride + ci0 + f4*4]
                               : make_float4(0.f, 0.f, 0.f, 0.f);
        }
#pragma unroll
        for (int i = 0; i < 2; i++) {
            int slot = i*256 + t;
            int kp = slot >> 5, f4 = slot & 31;
            int c0 = ci0 + kp*2;
            bx0[i] = *(const float4*)&X[((size_t)b*Ci + c0  )*NPTS + n0 + f4*4];
            bx1[i] = *(const float4*)&X[((size_t)b*Ci + c0+1)*NPTS + n0 + f4*4];
        }
    };

    auto sts_chunk = [&](int bufW, int ci0) {
        // A: [wh | wl] (wl only when SPLIT3)
#pragma unroll
        for (int i = 0; i < 2; i++) {
            int slot = i*256 + t;
            int co = slot >> 3, f4 = slot & 7;
            float4 w = aw[i];
            uint32_t h0 = cvt_h2(w.x, w.y);
            uint32_t h1 = cvt_h2(w.z, w.w);
            int wi = bufW + co*A_STR + f4*2;
            *(uint2*)&sm[wi] = make_uint2(h0, h1);        // wh
            if (SPLIT3) {
                uint32_t l0 = cvt_h2(w.x - lo_h2(h0), w.y - hi_h2(h0));
                uint32_t l1 = cvt_h2(w.z - lo_h2(h1), w.w - hi_h2(h1));
                *(uint2*)&sm[wi + 16] = make_uint2(l0, l1);   // wl
            }
        }
        // B: [xh | xl], BN+ReLU fused
#pragma unroll
        for (int i = 0; i < 2; i++) {
            int slot = i*256 + t;
            int kp = slot >> 5, f4 = slot & 31;
            int c0 = ci0 + kp*2;
            float s0 = scv[c0],   h0s = shv[c0];
            float s1 = scv[c0+1], h1s = shv[c0+1];
            float x0[4] = {bx0[i].x, bx0[i].y, bx0[i].z, bx0[i].w};
            float x1[4] = {bx1[i].x, bx1[i].y, bx1[i].z, bx1[i].w};
            uint32_t hw[4], lw[4];
#pragma unroll
            for (int j = 0; j < 4; j++) {
                float a0 = fmaxf(fmaf(x0[j], s0, h0s), 0.f);
                float a1 = fmaxf(fmaf(x1[j], s1, h1s), 0.f);
                uint32_t h = cvt_h2(a0, a1);
                hw[j] = h;
                lw[j] = cvt_h2(a0 - lo_h2(h), a1 - hi_h2(h));
            }
            int wi = bufW + B0_W + kp*B_STR + f4*4;
            *(uint4*)&sm[wi]            = make_uint4(hw[0], hw[1], hw[2], hw[3]); // xh
            *(uint4*)&sm[wi + 16*B_STR] = make_uint4(lw[0], lw[1], lw[2], lw[3]); // xl
        }
    };

    ldg_chunk(0);   // prologue

    // ldmatrix addressing (constant per thread)
    const int lrow = lane & 15;
    const int lkw  = (lane >> 4) * 4;

    for (int c = 0; c < nChunks; c++) {
        const int bufW = (c & 1) * SBUF_W;
        sts_chunk(bufW, c << 5);
        __syncthreads();                         // STS(c) visible to all warps
        if (c + 1 < nChunks) ldg_chunk((c+1) << 5);   // latency hidden by compute

        const uint32_t* Aw = sm + bufW;
        const uint32_t* Bx = sm + bufW + B0_W;

#pragma unroll
        for (int kg = 0; kg < 2; kg++) {         // k16 group within the chunk
            uint32_t ah[2][4], al[2][4];
#pragma unroll
            for (int mt = 0; mt < 2; mt++) {
                const uint32_t* base =
                    Aw + (warpM*32 + mt*16 + lrow) * A_STR + kg*8 + lkw;
                ldsm_x4(ah[mt], base);           // wh fragment
                if (SPLIT3) ldsm_x4(al[mt], base + 16);   // wl fragment
            }
            uint32_t bh[4][2], bl[4][2];
#pragma unroll
            for (int nt = 0; nt < 4; nt++) {
                int base = (kg*8 + q) * B_STR + warpN*32 + nt*8 + l4;
                bh[nt][0] = Bx[base];             bh[nt][1] = Bx[base + 4*B_STR];
                bl[nt][0] = Bx[base + 16*B_STR];  bl[nt][1] = Bx[base + 20*B_STR];
            }
#pragma unroll
            for (int mt = 0; mt < 2; mt++)
#pragma unroll
                for (int nt = 0; nt < 4; nt++) {
                    mma_f16(acc[mt][nt], ah[mt], bh[nt]);            // w*xh
                    mma_f16(acc[mt][nt], ah[mt], bl[nt]);            // w*xl
                    if (SPLIT3) mma_f16(acc[mt][nt], al[mt], bh[nt]); // wl*xh
                }
        }
    }

    // ---- epilogue: store Y + fused per-row stats partials ----
    const int tileIdx = blockIdx.y * 4 + warpN;
#pragma unroll
    for (int mt = 0; mt < 2; mt++) {
        int row0 = co0 + warpM*32 + mt*16 + l4;
        int row1 = row0 + 8;
        float bs0 = 0.f, bs1 = 0.f;
        if (row0 < Co) bs0 = biasPerBatch ? bias[(size_t)b*Co + row0] : bias[row0];
        if (row1 < Co) bs1 = biasPerBatch ? bias[(size_t)b*Co + row1] : bias[row1];
        float s0 = 0.f, q0 = 0.f, s1 = 0.f, q1 = 0.f;
#pragma unroll
        for (int nt = 0; nt < 4; nt++) {
            int col = n0 + warpN*32 + nt*8 + q*2;
            float o0 = acc[mt][nt][0] + bs0, o1 = acc[mt][nt][1] + bs0;
            float o2 = acc[mt][nt][2] + bs1, o3 = acc[mt][nt][3] + bs1;
            s0 += o0 + o1;  q0 = fmaf(o0, o0, q0); q0 = fmaf(o1, o1, q0);
            s1 += o2 + o3;  q1 = fmaf(o2, o2, q1); q1 = fmaf(o3, o3, q1);
            if (row0 < Co)
                *(float2*)&Y[((size_t)b*Co + row0)*NPTS + col] = make_float2(o0, o1);
            if (row1 < Co)
                *(float2*)&Y[((size_t)b*Co + row1)*NPTS + col] = make_float2(o2, o3);
        }
        s0 += __shfl_xor_sync(0xffffffffu, s0, 1);  s0 += __shfl_xor_sync(0xffffffffu, s0, 2);
        q0 += __shfl_xor_sync(0xffffffffu, q0, 1);  q0 += __shfl_xor_sync(0xffffffffu, q0, 2);
        s1 += __shfl_xor_sync(0xffffffffu, s1, 1);  s1 += __shfl_xor_sync(0xffffffffu, s1, 2);
        q1 += __shfl_xor_sync(0xffffffffu, q1, 1);  q1 += __shfl_xor_sync(0xffffffffu, q1, 2);
        if (q == 0) {
            if (row0 < Co) {
                g_hsum[(size_t)row0*HPT + tileIdx] = s0;
                g_hsq [(size_t)row0*HPT + tileIdx] = q0;
            }
            if (row1 < Co) {
                g_hsum[(size_t)row1*HPT + tileIdx] = s1;
                g_hsq [(size_t)row1*HPT + tileIdx] = q1;
            }
        }
    }
}

// ---------------- finalize3: reduce HPT partials -> BN scale/shift ----------
__global__ void __launch_bounds__(256)
finalize3_kernel(const float* __restrict__ gamma,
                 const float* __restrict__ beta, int layer)
{
    const int c = blockIdx.x;
    const int t = threadIdx.x;
    float s = 0.f, q = 0.f;
#pragma unroll
    for (int i = 0; i < HPT/256; i++) {
        s += g_hsum[(size_t)c * HPT + i*256 + t];
        q += g_hsq [(size_t)c * HPT + i*256 + t];
    }
    __shared__ float ss[256], sq[256];
    ss[t] = s; sq[t] = q;
    __syncthreads();
    for (int st = 128; st > 0; st >>= 1) {
        if (t < st) { ss[t] += ss[t + st]; sq[t] += sq[t + st]; }
        __syncthreads();
    }
    if (t == 0) {
        float m   = ss[0] * (1.0f / BNTOT);
        float var = sq[0] * (1.0f / BNTOT) - m * m;
        float rstd = rsqrtf(var + 1e-5f);
        float scl  = gamma[c] * rstd;
        g_scale[layer][c] = scl;
        g_shift[layer][c] = fmaf(-m, scl, beta[c]);
    }
}

// =================== fp32 FFMA2 GEMM (layer 1 only) ==========================
__global__ void __launch_bounds__(256, 2)
gemm_kernel(const float* __restrict__ W, int wstride,
            const float* __restrict__ bias,
            const float* __restrict__ X, int Ci,
            float* __restrict__ Y, int Co)
{
    __shared__ __align__(16) ull   As2[16][65];
    __shared__ __align__(16) float Xs[16][256];

    const int t  = threadIdx.x;
    const int tn = t & 15;
    const int r  = t >> 4;
    const int tilesPerBatch = NPTS / 256;
    const int b   = blockIdx.y / tilesPerBatch;
    const int n0  = (blockIdx.y % tilesPerBatch) * 256;
    const int co0 = blockIdx.x * 64;

    ull acc2[4][8];
#pragma unroll
    for (int j = 0; j < 4; j++)
#pragma unroll
        for (int qq = 0; qq < 8; qq++) acc2[j][qq] = 0ull;

    const int nChunks = (Ci + 15) >> 4;
    float  wreg[4];
    float4 xreg[4];

    {
#pragma unroll
        for (int i = 0; i < 4; i++) {
            int lin = i*256 + t;
            int k = lin & 15, co = lin >> 4;
            int ci = k, cog = co0 + co;
            wreg[i] = (ci < Ci && cog < Co) ? W[(size_t)cog * wstride + ci] : 0.f;
        }
#pragma unroll
        for (int i = 0; i < 4; i++) {
            int fidx = i*256 + t;
            int k  = fidx >> 6;
            int n4 = fidx & 63;
            xreg[i] = (k < Ci) ? *(const float4*)&X[((size_t)b * Ci + k) * NPTS + n0 + n4*4]
                               : make_float4(0.f,0.f,0.f,0.f);
        }
    }

    for (int c = 0; c < nChunks; c++) {
        const int k0 = c << 4;
        if (c > 0) __syncthreads();
#pragma unroll
        for (int i = 0; i < 4; i++) {
            int lin = i*256 + t;
            int k = lin & 15, co = lin >> 4;
            float w = wreg[i];
            As2[k][co] = pack2(w, w);
        }
#pragma unroll
        for (int i = 0; i < 4; i++) {
            int fidx = i*256 + t;
            int k  = fidx >> 6;
            int n4 = fidx & 63;
            *(float4*)&Xs[k][n4*4] = xreg[i];
        }
        __syncthreads();

        if (c + 1 < nChunks) {
            const int k0n = k0 + 16;
#pragma unroll
            for (int i = 0; i < 4; i++) {
                int lin = i*256 + t;
                int k = lin & 15, co = lin >> 4;
                int ci = k0n + k, cog = co0 + co;
                wreg[i] = (ci < Ci && cog < Co) ? W[(size_t)cog * wstride + ci] : 0.f;
            }
#pragma unroll
            for (int i = 0; i < 4; i++) {
                int fidx = i*256 + t;
                int k  = fidx >> 6;
                int n4 = fidx & 63;
                int ci = k0n + k;
                xreg[i] = (ci < Ci) ? *(const float4*)&X[((size_t)b * Ci + ci) * NPTS + n0 + n4*4]
                                    : make_float4(0.f,0.f,0.f,0.f);
            }
        }

#pragma unroll
        for (int kk = 0; kk < 16; kk++) {
            ull a0 = As2[kk][r*4 + 0];
            ull a1 = As2[kk][r*4 + 1];
            ull a2 = As2[kk][r*4 + 2];
            ull a3 = As2[kk][r*4 + 3];
#pragma unroll
            for (int g = 0; g < 4; g++) {
                ulonglong2 xv = *(const ulonglong2*)&Xs[kk][g*64 + tn*4];
                acc2[0][g*2+0] = fma2(a0, xv.x, acc2[0][g*2+0]);
                acc2[0][g*2+1] = fma2(a0, xv.y, acc2[0][g*2+1]);
                acc2[1][g*2+0] = fma2(a1, xv.x, acc2[1][g*2+0]);
                acc2[1][g*2+1] = fma2(a1, xv.y, acc2[1][g*2+1]);
                acc2[2][g*2+0] = fma2(a2, xv.x, acc2[2][g*2+0]);
                acc2[2][g*2+1] = fma2(a2, xv.y, acc2[2][g*2+1]);
                acc2[3][g*2+0] = fma2(a3, xv.x, acc2[3][g*2+0]);
                acc2[3][g*2+1] = fma2(a3, xv.y, acc2[3][g*2+1]);
            }
        }
    }

    const int tile = blockIdx.y;
#pragma unroll
    for (int j = 0; j < 4; j++) {
        int cog = co0 + r*4 + j;
        bool valid = (cog < Co);
        float bs = valid ? bias[cog] : 0.f;
        float s = 0.f, q = 0.f;
        float* yr = valid ? &Y[((size_t)b * Co + cog) * NPTS + n0] : (float*)0;
#pragma unroll
        for (int g = 0; g < 4; g++) {
            float4 o;
            unpack2(acc2[j][g*2+0], o.x, o.y);
            unpack2(acc2[j][g*2+1], o.z, o.w);
            o.x += bs; o.y += bs; o.z += bs; o.w += bs;
            s += (o.x + o.y) + (o.z + o.w);
            q = fmaf(o.x, o.x, q); q = fmaf(o.y, o.y, q);
            q = fmaf(o.z, o.z, q); q = fmaf(o.w, o.w, q);
            if (valid) *(float4*)&yr[g*64 + tn*4] = o;
        }
#pragma unroll
        for (int off = 8; off; off >>= 1) {
            s += __shfl_down_sync(0xffffffffu, s, off, 16);
            q += __shfl_down_sync(0xffffffffu, q, off, 16);
        }
        if (tn == 0 && valid) {
            g_bsum[(size_t)cog * NTILE + tile] = s;
            g_bsq [(size_t)cog * NTILE + tile] = q;
        }
    }
}

// ---------------- finalize for L1 ([c][NTILE]) -------------------------------
__global__ void __launch_bounds__(256)
finalize_kernel(const float* __restrict__ gamma,
                const float* __restrict__ beta, int layer)
{
    const int c = blockIdx.x;
    const int t = threadIdx.x;
    float s = 0.f, q = 0.f;
#pragma unroll
    for (int i = 0; i < NTILE/256; i++) {
        s += g_bsum[(size_t)c * NTILE + i*256 + t];
        q += g_bsq [(size_t)c * NTILE + i*256 + t];
    }
    __shared__ float ss[256], sq[256];
    ss[t] = s; sq[t] = q;
    __syncthreads();
    for (int st = 128; st > 0; st >>= 1) {
        if (t < st) { ss[t] += ss[t + st]; sq[t] += sq[t + st]; }
        __syncthreads();
    }
    if (t == 0) {
        float m   = ss[0] * (1.0f / BNTOT);
        float var = sq[0] * (1.0f / BNTOT) - m * m;
        float rstd = rsqrtf(var + 1e-5f);
        float scl  = gamma[c] * rstd;
        g_scale[layer][c] = scl;
        g_shift[layer][c] = fmaf(-m, scl, beta[c]);
    }
}

// ---------------- dedicated L7: 128 -> 3, tanh ------------------------------
__global__ void __launch_bounds__(256)
conv7_kernel(const float* __restrict__ w7, const float* __restrict__ b7,
             const float* __restrict__ Y6, float* __restrict__ out)
{
    __shared__ float sw0[128], sw1[128], sw2[128], ssc[128], ssh[128];
    const int t = threadIdx.x;
    if (t < 128) {
        sw0[t] = w7[t]; sw1[t] = w7[128 + t]; sw2[t] = w7[256 + t];
        ssc[t] = g_scale[5][t]; ssh[t] = g_shift[5][t];
    }
    __syncthreads();

    const int idx = blockIdx.x * 256 + t;        // 65536 threads, 4 pts each
    const int b = idx >> 12;
    const int n = (idx & 4095) * 4;

    float4 a0 = make_float4(0.f,0.f,0.f,0.f);
    float4 a1 = a0, a2 = a0;
#pragma unroll 4
    for (int c = 0; c < 128; c++) {
        float4 v = *(const float4*)&Y6[((size_t)b*128 + c)*NPTS + n];
        float s = ssc[c], h = ssh[c];
        v.x = fmaxf(fmaf(v.x, s, h), 0.f);
        v.y = fmaxf(fmaf(v.y, s, h), 0.f);
        v.z = fmaxf(fmaf(v.z, s, h), 0.f);
        v.w = fmaxf(fmaf(v.w, s, h), 0.f);
        float w0 = sw0[c], w1 = sw1[c], w2 = sw2[c];
        a0.x = fmaf(w0, v.x, a0.x); a0.y = fmaf(w0, v.y, a0.y);
        a0.z = fmaf(w0, v.z, a0.z); a0.w = fmaf(w0, v.w, a0.w);
        a1.x = fmaf(w1, v.x, a1.x); a1.y = fmaf(w1, v.y, a1.y);
        a1.z = fmaf(w1, v.z, a1.z); a1.w = fmaf(w1, v.w, a1.w);
        a2.x = fmaf(w2, v.x, a2.x); a2.y = fmaf(w2, v.y, a2.y);
        a2.z = fmaf(w2, v.z, a2.z); a2.w = fmaf(w2, v.w, a2.w);
    }
    float b0 = b7[0], b1 = b7[1], b2 = b7[2];
    float4 o0 = make_float4(tanhf(a0.x+b0), tanhf(a0.y+b0), tanhf(a0.z+b0), tanhf(a0.w+b0));
    float4 o1 = make_float4(tanhf(a1.x+b1), tanhf(a1.y+b1), tanhf(a1.z+b1), tanhf(a1.w+b1));
    float4 o2 = make_float4(tanhf(a2.x+b2), tanhf(a2.y+b2), tanhf(a2.z+b2), tanhf(a2.w+b2));
    *(float4*)&out[((size_t)b*3 + 0)*NPTS + n] = o0;
    *(float4*)&out[((size_t)b*3 + 1)*NPTS + n] = o1;
    *(float4*)&out[((size_t)b*3 + 2)*NPTS + n] = o2;
}

// ---------------- SoftPool with smem row cache -------------------------------
__global__ void __launch_bounds__(256)
softpool_kernel(const float* __restrict__ w9, const float* __restrict__ b9)
{
    extern __shared__ float cache[];   // 16384 floats (64 KB)
    const int b = blockIdx.x >> 5;
    const int k = blockIdx.x & 31;
    const int t = threadIdx.x;

    __shared__ float sVal[256];
    __shared__ int   sIdx[256];
    __shared__ int   selIdx[16];

    const float sc = g_scale[2][k], sh = g_shift[2][k];
    const float* __restrict__ row = &g_y3[((size_t)b * 32 + k) * NPTS];

    for (int n = t; n < NPTS; n += 256) cache[n] = fmaf(row[n], sc, sh);
    __syncthreads();

    float lastV = -3.402823466e38f;
    int   lastI = -1;

    for (int p = 0; p < 16; p++) {
        float bv = 3.402823466e38f;
        int   bi = NPTS;
        for (int n = t; n < NPTS; n += 256) {
            float val = cache[n];
            bool elig = (val > lastV) || (val == lastV && n > lastI);
            if (elig && (val < bv || (val == bv && n < bi))) { bv = val; bi = n; }
        }
        sVal[t] = bv; sIdx[t] = bi;
        __syncthreads();
        for (int st = 128; st > 0; st >>= 1) {
            if (t < st) {
                float ov = sVal[t + st]; int oi = sIdx[t + st];
                if (ov < sVal[t] || (ov == sVal[t] && oi < sIdx[t])) { sVal[t] = ov; sIdx[t] = oi; }
            }
            __syncthreads();
        }
        lastV = sVal[0]; lastI = sIdx[0];
        if (t == 0) selIdx[p] = sIdx[0];
        __syncthreads();
    }

    float part = 0.f;
    for (int i = t; i < 512; i += 256) {
        int c = i >> 4, p = i & 15;
        int n = selIdx[p];
        float val = fmaf(g_y3[((size_t)b * 32 + c) * NPTS + n], g_scale[2][c], g_shift[2][c]);
        part = fmaf(w9[c * 16 + p], val, part);
    }
    sVal[t] = part;
    __syncthreads();
    for (int st = 128; st > 0; st >>= 1) {
        if (t < st) sVal[t] += sVal[t + st];
        __syncthreads();
    }
    if (t == 0) g_v[b * 32 + k] = sVal[0] + b9[0];
}

// ---------------- fold glob into conv4 bias ---------------------------------
__global__ void bias4_kernel(const float* __restrict__ w4, const float* __restrict__ b4)
{
    int idx = blockIdx.x * 256 + threadIdx.x;
    if (idx >= BATCH * 512) return;
    int b = idx >> 9, co = idx & 511;
    float s = b4[co];
#pragma unroll
    for (int k = 0; k < 32; k++) s = fmaf(w4[co * 96 + k], g_v[b * 32 + k], s);
    g_bias4[idx] = s;
}

// ---------------------------------------------------------------------------
extern "C" void kernel_launch(void* const* d_in, const int* in_sizes, int n_in,
                              void* d_out, int out_size)
{
    const float* x   = (const float*)d_in[0];
    const float* w1  = (const float*)d_in[1];  const float* b1  = (const float*)d_in[2];
    const float* g1  = (const float*)d_in[3];  const float* be1 = (const float*)d_in[4];
    const float* w2  = (const float*)d_in[5];  const float* b2  = (const float*)d_in[6];
    const float* g2  = (const float*)d_in[7];  const float* be2 = (const float*)d_in[8];
    const float* w3  = (const float*)d_in[9];  const float* b3  = (const float*)d_in[10];
    const float* g3  = (const float*)d_in[11]; const float* be3 = (const float*)d_in[12];
    const float* w9  = (const float*)d_in[13]; const float* b9  = (const float*)d_in[14];
    const float* w4  = (const float*)d_in[15]; const float* b4  = (const float*)d_in[16];
    const float* g4  = (const float*)d_in[17]; const float* be4 = (const float*)d_in[18];
    const float* w5  = (const float*)d_in[19]; const float* b5  = (const float*)d_in[20];
    const float* g5  = (const float*)d_in[21]; const float* be5 = (const float*)d_in[22];
    const float* w6  = (const float*)d_in[23]; const float* b6  = (const float*)d_in[24];
    const float* g6  = (const float*)d_in[25]; const float* be6 = (const float*)d_in[26];
    const float* w7  = (const float*)d_in[27]; const float* b7  = (const float*)d_in[28];

    float *y1, *y2, *y3, *y4, *y5, *y6, *bias4p;
    cudaGetSymbolAddress((void**)&y1, g_y1);
    cudaGetSymbolAddress((void**)&y2, g_y2);
    cudaGetSymbolAddress((void**)&y3, g_y3);
    cudaGetSymbolAddress((void**)&y4, g_y4);
    cudaGetSymbolAddress((void**)&y5, g_y5);
    cudaGetSymbolAddress((void**)&y6, g_y6);
    cudaGetSymbolAddress((void**)&bias4p, g_bias4);

    const int SMEM = 2 * SBUF_W * 4;   // 53248 B
    cudaFuncSetAttribute(hmma_gemm_kernel<true>,  cudaFuncAttributeMaxDynamicSharedMemorySize, SMEM);
    cudaFuncSetAttribute(hmma_gemm_kernel<false>, cudaFuncAttributeMaxDynamicSharedMemorySize, SMEM);
    const int SPSM = NPTS * 4;         // 65536 B
    cudaFuncSetAttribute(softpool_kernel, cudaFuncAttributeMaxDynamicSharedMemorySize, SPSM);

    const dim3 blk(256);

    // L1: 4 -> 64 (fp32, fused stats)
    gemm_kernel<<<dim3(1, NTILE), blk>>>(w1, 4, b1, x, 4, y1, 64);
    finalize_kernel<<<64, 256>>>(g1, be1, 0);

    // L2: 64 -> 128 (3-term: feeds softpool selection)
    hmma_gemm_kernel<true><<<dim3(2, 2048), blk, SMEM>>>(w2, 64, b2, 0, y1, 64, 0, y2, 128);
    finalize3_kernel<<<128, 256>>>(g2, be2, 1);

    // L3: 128 -> 32 (3-term: feeds softpool selection)
    hmma_gemm_kernel<true><<<dim3(1, 2048), blk, SMEM>>>(w3, 128, b3, 0, y2, 128, 1, y3, 32);
    finalize3_kernel<<<32, 256>>>(g3, be3, 2);

    // SoftPool + fold glob into conv4 bias
    softpool_kernel<<<512, 256, SPSM>>>(w9, b9);
    bias4_kernel<<<32, 256>>>(w4, b4);

    // L4: 64 -> 512 (2-term: post-softpool, smooth path)
    hmma_gemm_kernel<false><<<dim3(8, 2048), blk, SMEM>>>(w4 + 32, 96, bias4p, 1, y1, 64, 0, y4, 512);
    finalize3_kernel<<<512, 256>>>(g4, be4, 3);

    // L5: 512 -> 256 (2-term: post-softpool, smooth path)
    hmma_gemm_kernel<false><<<dim3(4, 2048), blk, SMEM>>>(w5, 512, b5, 0, y4, 512, 3, y5, 256);
    finalize3_kernel<<<256, 256>>>(g5, be5, 4);

    // L6: 256 -> 128 (3-term: keep output-path error budget in reserve)
    hmma_gemm_kernel<true><<<dim3(2, 2048), blk, SMEM>>>(w6, 256, b6, 0, y5, 256, 4, y6, 128);
    finalize3_kernel<<<128, 256>>>(g6, be6, 5);

    // L7: 128 -> 3, tanh, dedicated kernel, straight to output
    conv7_kernel<<<BNTOT/4/256, blk>>>(w7, b7, y6, (float*)d_out);
}

// round 13
// speedup vs baseline: 1.1639x; 1.0477x over previous
#include <cuda_runtime.h>
#include <cuda_fp16.h>
#include <math.h>
#include <stdint.h>

#define BATCH 16
#define NPTS  16384
#define BNTOT (BATCH*NPTS)
#define NTILE (BNTOT/256)   // 1024 column tiles (fp32 gemm path)
#define HPT   8192          // hmma stats partials per channel

typedef unsigned long long ull;

// ---------------- packed f32x2 / fp16 helpers --------------------------------
__device__ __forceinline__ ull pack2(float lo, float hi) {
    ull r; asm("mov.b64 %0, {%1, %2};" : "=l"(r) : "f"(lo), "f"(hi)); return r;
}
__device__ __forceinline__ ull fma2(ull a, ull b, ull c) {
    ull d; asm("fma.rn.f32x2 %0, %1, %2, %3;" : "=l"(d) : "l"(a), "l"(b), "l"(c)); return d;
}
__device__ __forceinline__ void unpack2(ull v, float& lo, float& hi) {
    asm("mov.b64 {%0, %1}, %2;" : "=f"(lo), "=f"(hi) : "l"(v));
}
__device__ __forceinline__ uint32_t cvt_h2(float lo, float hi) {
    uint32_t r;
    asm("cvt.rn.satfinite.f16x2.f32 %0, %1, %2;" : "=r"(r) : "f"(hi), "f"(lo));
    return r;
}
__device__ __forceinline__ float lo_h2(uint32_t h) {
    __half2 hh = *reinterpret_cast<const __half2*>(&h);
    return __low2float(hh);
}
__device__ __forceinline__ float hi_h2(uint32_t h) {
    __half2 hh = *reinterpret_cast<const __half2*>(&h);
    return __high2float(hh);
}
__device__ __forceinline__ void mma_f16(float d[4], const uint32_t a[4], const uint32_t b[2]) {
    asm volatile("mma.sync.aligned.m16n8k16.row.col.f32.f16.f16.f32 "
        "{%0,%1,%2,%3}, {%4,%5,%6,%7}, {%8,%9}, {%0,%1,%2,%3};"
        : "+f"(d[0]), "+f"(d[1]), "+f"(d[2]), "+f"(d[3])
        : "r"(a[0]), "r"(a[1]), "r"(a[2]), "r"(a[3]), "r"(b[0]), "r"(b[1]));
}
// canonical A-fragment load: 16x16 f16 tile, rows contiguous in smem
__device__ __forceinline__ void ldsm_x4(uint32_t r[4], const uint32_t* p) {
    uint32_t a = (uint32_t)__cvta_generic_to_shared(p);
    asm volatile("ldmatrix.sync.aligned.m8n8.x4.shared.b16 {%0,%1,%2,%3}, [%4];"
        : "=r"(r[0]), "=r"(r[1]), "=r"(r[2]), "=r"(r[3]) : "r"(a));
}

// ---------------- scratch (device globals) ----------------------------------
__device__ float g_y1[(size_t)BATCH*64*NPTS];
__device__ float g_y2[(size_t)BATCH*128*NPTS];
__device__ float g_y3[(size_t)BATCH*32*NPTS];
__device__ float g_y4[(size_t)BATCH*512*NPTS];
__device__ float g_y5[(size_t)BATCH*256*NPTS];
__device__ float g_y6[(size_t)BATCH*128*NPTS];
__device__ float g_bsum[(size_t)64*NTILE];      // L1 fused stats [c][tile]
__device__ float g_bsq [(size_t)64*NTILE];
__device__ float g_hsum[(size_t)512*HPT];       // hmma fused stats [c][tile*4+warpN]
__device__ float g_hsq [(size_t)512*HPT];
__device__ float g_scale[6][512];
__device__ float g_shift[6][512];
__device__ float g_v[BATCH*32];
__device__ float g_bias4[BATCH*512];

// =================== HMMA fp16 split GEMM (layers 2-6) =======================
// A = [wh(16w) | wl(16w)] always (weights split in smem).
// SPLIT3=true : B = [xh | xl];  D = wh*xh + wh*xl + wl*xh  (48 MMA/chunk,
//               ~2e-6) -- layers feeding the softpool argsort (L2,L3).
// SPLIT3=false: B = x16 (acts rounded once); D = wh*x + wl*x (32 MMA/chunk,
//               ~2.8e-4/layer) -- post-softpool smooth layers (L4,L5,L6).
//               Halves B staging + B LDS vs the SPLIT3 path.
#define A_STR   36               // 32 data words + 4 pad
#define B_STR   136              // 128 data words + 8 pad
#define B0_W    2304             // A region = 64*36 words
#define SBUF3_W 6656             // A + B(32 rows)  -- SPLIT3 buffer words
#define SBUF2_W 4480             // A + B(16 rows)  -- 2-term buffer words

template<bool SPLIT3>
__global__ void __launch_bounds__(256, 2)
hmma_gemm_kernel(const float* __restrict__ W, int wstride,
                 const float* __restrict__ bias, int biasPerBatch,
                 const float* __restrict__ X, int Ci, int inLayer,
                 float* __restrict__ Y, int Co)
{
    extern __shared__ uint32_t sm[];
    constexpr int SBUF_W = SPLIT3 ? SBUF3_W : SBUF2_W;
    const int t    = threadIdx.x;
    const int lane = t & 31, wid = t >> 5;
    const int warpM = wid & 1, warpN = wid >> 1;   // 2 x 4 warps, warp tile 32x32
    const int l4 = lane >> 2, q = lane & 3;
    const int b   = blockIdx.y >> 7;
    const int n0  = (blockIdx.y & 127) * 128;
    const int co0 = blockIdx.x * 64;

    const float* __restrict__ scv = g_scale[inLayer];
    const float* __restrict__ shv = g_shift[inLayer];
    const int nChunks = Ci >> 5;

    float acc[2][4][4];
#pragma unroll
    for (int mt = 0; mt < 2; mt++)
#pragma unroll
        for (int nt = 0; nt < 4; nt++)
#pragma unroll
            for (int j = 0; j < 4; j++) acc[mt][nt][j] = 0.f;

    // register staging for the in-flight chunk
    float4 aw[2];           // weights
    float4 bx0[2], bx1[2];  // activations (channel pair)

    auto ldg_chunk = [&](int ci0) {
#pragma unroll
        for (int i = 0; i < 2; i++) {
            int slot = i*256 + t;
            int co = slot >> 3, f4 = slot & 7;
            int cog = co0 + co;
            aw[i] = (cog < Co) ? *(const float4*)&W[(size_t)cog*wstride + ci0 + f4*4]
                               : make_float4(0.f, 0.f, 0.f, 0.f);
        }
#pragma unroll
        for (int i = 0; i < 2; i++) {
            int slot = i*256 + t;
            int kp = slot >> 5, f4 = slot & 31;
            int c0 = ci0 + kp*2;
            bx0[i] = *(const float4*)&X[((size_t)b*Ci + c0  )*NPTS + n0 + f4*4];
            bx1[i] = *(const float4*)&X[((size_t)b*Ci + c0+1)*NPTS + n0 + f4*4];
        }
    };

    auto sts_chunk = [&](int bufW, int ci0) {
        // A: [wh | wl]
#pragma unroll
        for (int i = 0; i < 2; i++) {
            int slot = i*256 + t;
            int co = slot >> 3, f4 = slot & 7;
            float4 w = aw[i];
            uint32_t h0 = cvt_h2(w.x, w.y);
            uint32_t h1 = cvt_h2(w.z, w.w);
            uint32_t l0 = cvt_h2(w.x - lo_h2(h0), w.y - hi_h2(h0));
            uint32_t l1 = cvt_h2(w.z - lo_h2(h1), w.w - hi_h2(h1));
            int wi = bufW + co*A_STR + f4*2;
            *(uint2*)&sm[wi]      = make_uint2(h0, h1);   // wh
            *(uint2*)&sm[wi + 16] = make_uint2(l0, l1);   // wl
        }
        // B: SPLIT3 -> [xh | xl]; else x16 only.  BN+ReLU fused.
#pragma unroll
        for (int i = 0; i < 2; i++) {
            int slot = i*256 + t;
            int kp = slot >> 5, f4 = slot & 31;
            int c0 = ci0 + kp*2;
            float s0 = scv[c0],   h0s = shv[c0];
            float s1 = scv[c0+1], h1s = shv[c0+1];
            float x0[4] = {bx0[i].x, bx0[i].y, bx0[i].z, bx0[i].w};
            float x1[4] = {bx1[i].x, bx1[i].y, bx1[i].z, bx1[i].w};
            uint32_t hw[4], lw[4];
#pragma unroll
            for (int j = 0; j < 4; j++) {
                float a0 = fmaxf(fmaf(x0[j], s0, h0s), 0.f);
                float a1 = fmaxf(fmaf(x1[j], s1, h1s), 0.f);
                uint32_t h = cvt_h2(a0, a1);
                hw[j] = h;
                if (SPLIT3) lw[j] = cvt_h2(a0 - lo_h2(h), a1 - hi_h2(h));
            }
            int wi = bufW + B0_W + kp*B_STR + f4*4;
            *(uint4*)&sm[wi] = make_uint4(hw[0], hw[1], hw[2], hw[3]);            // xh / x16
            if (SPLIT3)
                *(uint4*)&sm[wi + 16*B_STR] = make_uint4(lw[0], lw[1], lw[2], lw[3]); // xl
        }
    };

    ldg_chunk(0);   // prologue

    // ldmatrix addressing (constant per thread)
    const int lrow = lane & 15;
    const int lkw  = (lane >> 4) * 4;

    for (int c = 0; c < nChunks; c++) {
        const int bufW = (c & 1) * SBUF_W;
        sts_chunk(bufW, c << 5);
        __syncthreads();                         // STS(c) visible to all warps
        if (c + 1 < nChunks) ldg_chunk((c+1) << 5);   // latency hidden by compute

        const uint32_t* Aw = sm + bufW;
        const uint32_t* Bx = sm + bufW + B0_W;

#pragma unroll
        for (int kg = 0; kg < 2; kg++) {         // k16 group within the chunk
            uint32_t ah[2][4], al[2][4];
#pragma unroll
            for (int mt = 0; mt < 2; mt++) {
                const uint32_t* base =
                    Aw + (warpM*32 + mt*16 + lrow) * A_STR + kg*8 + lkw;
                ldsm_x4(ah[mt], base);           // wh fragment
                ldsm_x4(al[mt], base + 16);      // wl fragment
            }
            uint32_t bh[4][2], bl[4][2];
#pragma unroll
            for (int nt = 0; nt < 4; nt++) {
                int base = (kg*8 + q) * B_STR + warpN*32 + nt*8 + l4;
                bh[nt][0] = Bx[base];             bh[nt][1] = Bx[base + 4*B_STR];
                if (SPLIT3) {
                    bl[nt][0] = Bx[base + 16*B_STR];  bl[nt][1] = Bx[base + 20*B_STR];
                }
            }
#pragma unroll
            for (int mt = 0; mt < 2; mt++)
#pragma unroll
                for (int nt = 0; nt < 4; nt++) {
                    mma_f16(acc[mt][nt], ah[mt], bh[nt]);             // wh * x
                    if (SPLIT3) {
                        mma_f16(acc[mt][nt], ah[mt], bl[nt]);         // wh * xl
                        mma_f16(acc[mt][nt], al[mt], bh[nt]);         // wl * xh
                    } else {
                        mma_f16(acc[mt][nt], al[mt], bh[nt]);         // wl * x
                    }
                }
        }
    }

    // ---- epilogue: store Y + fused per-row stats partials ----
    const int tileIdx = blockIdx.y * 4 + warpN;
#pragma unroll
    for (int mt = 0; mt < 2; mt++) {
        int row0 = co0 + warpM*32 + mt*16 + l4;
        int row1 = row0 + 8;
        float bs0 = 0.f, bs1 = 0.f;
        if (row0 < Co) bs0 = biasPerBatch ? bias[(size_t)b*Co + row0] : bias[row0];
        if (row1 < Co) bs1 = biasPerBatch ? bias[(size_t)b*Co + row1] : bias[row1];
        float s0 = 0.f, q0 = 0.f, s1 = 0.f, q1 = 0.f;
#pragma unroll
        for (int nt = 0; nt < 4; nt++) {
            int col = n0 + warpN*32 + nt*8 + q*2;
            float o0 = acc[mt][nt][0] + bs0, o1 = acc[mt][nt][1] + bs0;
            float o2 = acc[mt][nt][2] + bs1, o3 = acc[mt][nt][3] + bs1;
            s0 += o0 + o1;  q0 = fmaf(o0, o0, q0); q0 = fmaf(o1, o1, q0);
            s1 += o2 + o3;  q1 = fmaf(o2, o2, q1); q1 = fmaf(o3, o3, q1);
            if (row0 < Co)
                *(float2*)&Y[((size_t)b*Co + row0)*NPTS + col] = make_float2(o0, o1);
            if (row1 < Co)
                *(float2*)&Y[((size_t)b*Co + row1)*NPTS + col] = make_float2(o2, o3);
        }
        s0 += __shfl_xor_sync(0xffffffffu, s0, 1);  s0 += __shfl_xor_sync(0xffffffffu, s0, 2);
        q0 += __shfl_xor_sync(0xffffffffu, q0, 1);  q0 += __shfl_xor_sync(0xffffffffu, q0, 2);
        s1 += __shfl_xor_sync(0xffffffffu, s1, 1);  s1 += __shfl_xor_sync(0xffffffffu, s1, 2);
        q1 += __shfl_xor_sync(0xffffffffu, q1, 1);  q1 += __shfl_xor_sync(0xffffffffu, q1, 2);
        if (q == 0) {
            if (row0 < Co) {
                g_hsum[(size_t)row0*HPT + tileIdx] = s0;
                g_hsq [(size_t)row0*HPT + tileIdx] = q0;
            }
            if (row1 < Co) {
                g_hsum[(size_t)row1*HPT + tileIdx] = s1;
                g_hsq [(size_t)row1*HPT + tileIdx] = q1;
            }
        }
    }
}

// ---------------- finalize3: reduce HPT partials -> BN scale/shift ----------
__global__ void __launch_bounds__(256)
finalize3_kernel(const float* __restrict__ gamma,
                 const float* __restrict__ beta, int layer)
{
    const int c = blockIdx.x;
    const int t = threadIdx.x;
    float s = 0.f, q = 0.f;
#pragma unroll
    for (int i = 0; i < HPT/256; i++) {
        s += g_hsum[(size_t)c * HPT + i*256 + t];
        q += g_hsq [(size_t)c * HPT + i*256 + t];
    }
    __shared__ float ss[256], sq[256];
    ss[t] = s; sq[t] = q;
    __syncthreads();
    for (int st = 128; st > 0; st >>= 1) {
        if (t < st) { ss[t] += ss[t + st]; sq[t] += sq[t + st]; }
        __syncthreads();
    }
    if (t == 0) {
        float m   = ss[0] * (1.0f / BNTOT);
        float var = sq[0] * (1.0f / BNTOT) - m * m;
        float rstd = rsqrtf(var + 1e-5f);
        float scl  = gamma[c] * rstd;
        g_scale[layer][c] = scl;
        g_shift[layer][c] = fmaf(-m, scl, beta[c]);
    }
}

// =================== fp32 FFMA2 GEMM (layer 1 only) ==========================
__global__ void __launch_bounds__(256, 2)
gemm_kernel(const float* __restrict__ W, int wstride,
            const float* __restrict__ bias,
            const float* __restrict__ X, int Ci,
            float* __restrict__ Y, int Co)
{
    __shared__ __align__(16) ull   As2[16][65];
    __shared__ __align__(16) float Xs[16][256];

    const int t  = threadIdx.x;
    const int tn = t & 15;
    const int r  = t >> 4;
    const int tilesPerBatch = NPTS / 256;
    const int b   = blockIdx.y / tilesPerBatch;
    const int n0  = (blockIdx.y % tilesPerBatch) * 256;
    const int co0 = blockIdx.x * 64;

    ull acc2[4][8];
#pragma unroll
    for (int j = 0; j < 4; j++)
#pragma unroll
        for (int qq = 0; qq < 8; qq++) acc2[j][qq] = 0ull;

    const int nChunks = (Ci + 15) >> 4;
    float  wreg[4];
    float4 xreg[4];

    {
#pragma unroll
        for (int i = 0; i < 4; i++) {
            int lin = i*256 + t;
            int k = lin & 15, co = lin >> 4;
            int ci = k, cog = co0 + co;
            wreg[i] = (ci < Ci && cog < Co) ? W[(size_t)cog * wstride + ci] : 0.f;
        }
#pragma unroll
        for (int i = 0; i < 4; i++) {
            int fidx = i*256 + t;
            int k  = fidx >> 6;
            int n4 = fidx & 63;
            xreg[i] = (k < Ci) ? *(const float4*)&X[((size_t)b * Ci + k) * NPTS + n0 + n4*4]
                               : make_float4(0.f,0.f,0.f,0.f);
        }
    }

    for (int c = 0; c < nChunks; c++) {
        const int k0 = c << 4;
        if (c > 0) __syncthreads();
#pragma unroll
        for (int i = 0; i < 4; i++) {
            int lin = i*256 + t;
            int k = lin & 15, co = lin >> 4;
            float w = wreg[i];
            As2[k][co] = pack2(w, w);
        }
#pragma unroll
        for (int i = 0; i < 4; i++) {
            int fidx = i*256 + t;
            int k  = fidx >> 6;
            int n4 = fidx & 63;
            *(float4*)&Xs[k][n4*4] = xreg[i];
        }
        __syncthreads();

        if (c + 1 < nChunks) {
            const int k0n = k0 + 16;
#pragma unroll
            for (int i = 0; i < 4; i++) {
                int lin = i*256 + t;
                int k = lin & 15, co = lin >> 4;
                int ci = k0n + k, cog = co0 + co;
                wreg[i] = (ci < Ci && cog < Co) ? W[(size_t)cog * wstride + ci] : 0.f;
            }
#pragma unroll
            for (int i = 0; i < 4; i++) {
                int fidx = i*256 + t;
                int k  = fidx >> 6;
                int n4 = fidx & 63;
                int ci = k0n + k;
                xreg[i] = (ci < Ci) ? *(const float4*)&X[((size_t)b * Ci + ci) * NPTS + n0 + n4*4]
                                    : make_float4(0.f,0.f,0.f,0.f);
            }
        }

#pragma unroll
        for (int kk = 0; kk < 16; kk++) {
            ull a0 = As2[kk][r*4 + 0];
            ull a1 = As2[kk][r*4 + 1];
            ull a2 = As2[kk][r*4 + 2];
            ull a3 = As2[kk][r*4 + 3];
#pragma unroll
            for (int g = 0; g < 4; g++) {
                ulonglong2 xv = *(const ulonglong2*)&Xs[kk][g*64 + tn*4];
                acc2[0][g*2+0] = fma2(a0, xv.x, acc2[0][g*2+0]);
                acc2[0][g*2+1] = fma2(a0, xv.y, acc2[0][g*2+1]);
                acc2[1][g*2+0] = fma2(a1, xv.x, acc2[1][g*2+0]);
                acc2[1][g*2+1] = fma2(a1, xv.y, acc2[1][g*2+1]);
                acc2[2][g*2+0] = fma2(a2, xv.x, acc2[2][g*2+0]);
                acc2[2][g*2+1] = fma2(a2, xv.y, acc2[2][g*2+1]);
                acc2[3][g*2+0] = fma2(a3, xv.x, acc2[3][g*2+0]);
                acc2[3][g*2+1] = fma2(a3, xv.y, acc2[3][g*2+1]);
            }
        }
    }

    const int tile = blockIdx.y;
#pragma unroll
    for (int j = 0; j < 4; j++) {
        int cog = co0 + r*4 + j;
        bool valid = (cog < Co);
        float bs = valid ? bias[cog] : 0.f;
        float s = 0.f, q = 0.f;
        float* yr = valid ? &Y[((size_t)b * Co + cog) * NPTS + n0] : (float*)0;
#pragma unroll
        for (int g = 0; g < 4; g++) {
            float4 o;
            unpack2(acc2[j][g*2+0], o.x, o.y);
            unpack2(acc2[j][g*2+1], o.z, o.w);
            o.x += bs; o.y += bs; o.z += bs; o.w += bs;
            s += (o.x + o.y) + (o.z + o.w);
            q = fmaf(o.x, o.x, q); q = fmaf(o.y, o.y, q);
            q = fmaf(o.z, o.z, q); q = fmaf(o.w, o.w, q);
            if (valid) *(float4*)&yr[g*64 + tn*4] = o;
        }
#pragma unroll
        for (int off = 8; off; off >>= 1) {
            s += __shfl_down_sync(0xffffffffu, s, off, 16);
            q += __shfl_down_sync(0xffffffffu, q, off, 16);
        }
        if (tn == 0 && valid) {
            g_bsum[(size_t)cog * NTILE + tile] = s;
            g_bsq [(size_t)cog * NTILE + tile] = q;
        }
    }
}

// ---------------- finalize for L1 ([c][NTILE]) -------------------------------
__global__ void __launch_bounds__(256)
finalize_kernel(const float* __restrict__ gamma,
                const float* __restrict__ beta, int layer)
{
    const int c = blockIdx.x;
    const int t = threadIdx.x;
    float s = 0.f, q = 0.f;
#pragma unroll
    for (int i = 0; i < NTILE/256; i++) {
        s += g_bsum[(size_t)c * NTILE + i*256 + t];
        q += g_bsq [(size_t)c * NTILE + i*256 + t];
    }
    __shared__ float ss[256], sq[256];
    ss[t] = s; sq[t] = q;
    __syncthreads();
    for (int st = 128; st > 0; st >>= 1) {
        if (t < st) { ss[t] += ss[t + st]; sq[t] += sq[t + st]; }
        __syncthreads();
    }
    if (t == 0) {
        float m   = ss[0] * (1.0f / BNTOT);
        float var = sq[0] * (1.0f / BNTOT) - m * m;
        float rstd = rsqrtf(var + 1e-5f);
        float scl  = gamma[c] * rstd;
        g_scale[layer][c] = scl;
        g_shift[layer][c] = fmaf(-m, scl, beta[c]);
    }
}

// ---------------- dedicated L7: 128 -> 3, tanh ------------------------------
__global__ void __launch_bounds__(256)
conv7_kernel(const float* __restrict__ w7, const float* __restrict__ b7,
             const float* __restrict__ Y6, float* __restrict__ out)
{
    __shared__ float sw0[128], sw1[128], sw2[128], ssc[128], ssh[128];
    const int t = threadIdx.x;
    if (t < 128) {
        sw0[t] = w7[t]; sw1[t] = w7[128 + t]; sw2[t] = w7[256 + t];
        ssc[t] = g_scale[5][t]; ssh[t] = g_shift[5][t];
    }
    __syncthreads();

    const int idx = blockIdx.x * 256 + t;        // 65536 threads, 4 pts each
    const int b = idx >> 12;
    const int n = (idx & 4095) * 4;

    float4 a0 = make_float4(0.f,0.f,0.f,0.f);
    float4 a1 = a0, a2 = a0;
#pragma unroll 4
    for (int c = 0; c < 128; c++) {
        float4 v = *(const float4*)&Y6[((size_t)b*128 + c)*NPTS + n];
        float s = ssc[c], h = ssh[c];
        v.x = fmaxf(fmaf(v.x, s, h), 0.f);
        v.y = fmaxf(fmaf(v.y, s, h), 0.f);
        v.z = fmaxf(fmaf(v.z, s, h), 0.f);
        v.w = fmaxf(fmaf(v.w, s, h), 0.f);
        float w0 = sw0[c], w1 = sw1[c], w2 = sw2[c];
        a0.x = fmaf(w0, v.x, a0.x); a0.y = fmaf(w0, v.y, a0.y);
        a0.z = fmaf(w0, v.z, a0.z); a0.w = fmaf(w0, v.w, a0.w);
        a1.x = fmaf(w1, v.x, a1.x); a1.y = fmaf(w1, v.y, a1.y);
        a1.z = fmaf(w1, v.z, a1.z); a1.w = fmaf(w1, v.w, a1.w);
        a2.x = fmaf(w2, v.x, a2.x); a2.y = fmaf(w2, v.y, a2.y);
        a2.z = fmaf(w2, v.z, a2.z); a2.w = fmaf(w2, v.w, a2.w);
    }
    float b0 = b7[0], b1 = b7[1], b2 = b7[2];
    float4 o0 = make_float4(tanhf(a0.x+b0), tanhf(a0.y+b0), tanhf(a0.z+b0), tanhf(a0.w+b0));
    float4 o1 = make_float4(tanhf(a1.x+b1), tanhf(a1.y+b1), tanhf(a1.z+b1), tanhf(a1.w+b1));
    float4 o2 = make_float4(tanhf(a2.x+b2), tanhf(a2.y+b2), tanhf(a2.z+b2), tanhf(a2.w+b2));
    *(float4*)&out[((size_t)b*3 + 0)*NPTS + n] = o0;
    *(float4*)&out[((size_t)b*3 + 1)*NPTS + n] = o1;
    *(float4*)&out[((size_t)b*3 + 2)*NPTS + n] = o2;
}

// ---------------- SoftPool with smem row cache -------------------------------
__global__ void __launch_bounds__(256)
softpool_kernel(const float* __restrict__ w9, const float* __restrict__ b9)
{
    extern __shared__ float cache[];   // 16384 floats (64 KB)
    const int b = blockIdx.x >> 5;
    const int k = blockIdx.x & 31;
    const int t = threadIdx.x;

    __shared__ float sVal[256];
    __shared__ int   sIdx[256];
    __shared__ int   selIdx[16];

    const float sc = g_scale[2][k], sh = g_shift[2][k];
    const float* __restrict__ row = &g_y3[((size_t)b * 32 + k) * NPTS];

    for (int n = t; n < NPTS; n += 256) cache[n] = fmaf(row[n], sc, sh);
    __syncthreads();

    float lastV = -3.402823466e38f;
    int   lastI = -1;

    for (int p = 0; p < 16; p++) {
        float bv = 3.402823466e38f;
        int   bi = NPTS;
        for (int n = t; n < NPTS; n += 256) {
            float val = cache[n];
            bool elig = (val > lastV) || (val == lastV && n > lastI);
            if (elig && (val < bv || (val == bv && n < bi))) { bv = val; bi = n; }
        }
        sVal[t] = bv; sIdx[t] = bi;
        __syncthreads();
        for (int st = 128; st > 0; st >>= 1) {
            if (t < st) {
                float ov = sVal[t + st]; int oi = sIdx[t + st];
                if (ov < sVal[t] || (ov == sVal[t] && oi < sIdx[t])) { sVal[t] = ov; sIdx[t] = oi; }
            }
            __syncthreads();
        }
        lastV = sVal[0]; lastI = sIdx[0];
        if (t == 0) selIdx[p] = sIdx[0];
        __syncthreads();
    }

    float part = 0.f;
    for (int i = t; i < 512; i += 256) {
        int c = i >> 4, p = i & 15;
        int n = selIdx[p];
        float val = fmaf(g_y3[((size_t)b * 32 + c) * NPTS + n], g_scale[2][c], g_shift[2][c]);
        part = fmaf(w9[c * 16 + p], val, part);
    }
    sVal[t] = part;
    __syncthreads();
    for (int st = 128; st > 0; st >>= 1) {
        if (t < st) sVal[t] += sVal[t + st];
        __syncthreads();
    }
    if (t == 0) g_v[b * 32 + k] = sVal[0] + b9[0];
}

// ---------------- fold glob into conv4 bias ---------------------------------
__global__ void bias4_kernel(const float* __restrict__ w4, const float* __restrict__ b4)
{
    int idx = blockIdx.x * 256 + threadIdx.x;
    if (idx >= BATCH * 512) return;
    int b = idx >> 9, co = idx & 511;
    float s = b4[co];
#pragma unroll
    for (int k = 0; k < 32; k++) s = fmaf(w4[co * 96 + k], g_v[b * 32 + k], s);
    g_bias4[idx] = s;
}

// ---------------------------------------------------------------------------
extern "C" void kernel_launch(void* const* d_in, const int* in_sizes, int n_in,
                              void* d_out, int out_size)
{
    const float* x   = (const float*)d_in[0];
    const float* w1  = (const float*)d_in[1];  const float* b1  = (const float*)d_in[2];
    const float* g1  = (const float*)d_in[3];  const float* be1 = (const float*)d_in[4];
    const float* w2  = (const float*)d_in[5];  const float* b2  = (const float*)d_in[6];
    const float* g2  = (const float*)d_in[7];  const float* be2 = (const float*)d_in[8];
    const float* w3  = (const float*)d_in[9];  const float* b3  = (const float*)d_in[10];
    const float* g3  = (const float*)d_in[11]; const float* be3 = (const float*)d_in[12];
    const float* w9  = (const float*)d_in[13]; const float* b9  = (const float*)d_in[14];
    const float* w4  = (const float*)d_in[15]; const float* b4  = (const float*)d_in[16];
    const float* g4  = (const float*)d_in[17]; const float* be4 = (const float*)d_in[18];
    const float* w5  = (const float*)d_in[19]; const float* b5  = (const float*)d_in[20];
    const float* g5  = (const float*)d_in[21]; const float* be5 = (const float*)d_in[22];
    const float* w6  = (const float*)d_in[23]; const float* b6  = (const float*)d_in[24];
    const float* g6  = (const float*)d_in[25]; const float* be6 = (const float*)d_in[26];
    const float* w7  = (const float*)d_in[27]; const float* b7  = (const float*)d_in[28];

    float *y1, *y2, *y3, *y4, *y5, *y6, *bias4p;
    cudaGetSymbolAddress((void**)&y1, g_y1);
    cudaGetSymbolAddress((void**)&y2, g_y2);
    cudaGetSymbolAddress((void**)&y3, g_y3);
    cudaGetSymbolAddress((void**)&y4, g_y4);
    cudaGetSymbolAddress((void**)&y5, g_y5);
    cudaGetSymbolAddress((void**)&y6, g_y6);
    cudaGetSymbolAddress((void**)&bias4p, g_bias4);

    const int SMEM3 = 2 * SBUF3_W * 4;   // 53248 B
    const int SMEM2 = 2 * SBUF2_W * 4;   // 35840 B
    cudaFuncSetAttribute(hmma_gemm_kernel<true>,  cudaFuncAttributeMaxDynamicSharedMemorySize, SMEM3);
    cudaFuncSetAttribute(hmma_gemm_kernel<false>, cudaFuncAttributeMaxDynamicSharedMemorySize, SMEM2);
    const int SPSM = NPTS * 4;           // 65536 B
    cudaFuncSetAttribute(softpool_kernel, cudaFuncAttributeMaxDynamicSharedMemorySize, SPSM);

    const dim3 blk(256);

    // L1: 4 -> 64 (fp32, fused stats)
    gemm_kernel<<<dim3(1, NTILE), blk>>>(w1, 4, b1, x, 4, y1, 64);
    finalize_kernel<<<64, 256>>>(g1, be1, 0);

    // L2: 64 -> 128 (3-term: feeds softpool selection)
    hmma_gemm_kernel<true><<<dim3(2, 2048), blk, SMEM3>>>(w2, 64, b2, 0, y1, 64, 0, y2, 128);
    finalize3_kernel<<<128, 256>>>(g2, be2, 1);

    // L3: 128 -> 32 (3-term: feeds softpool selection)
    hmma_gemm_kernel<true><<<dim3(1, 2048), blk, SMEM3>>>(w3, 128, b3, 0, y2, 128, 1, y3, 32);
    finalize3_kernel<<<32, 256>>>(g3, be3, 2);

    // SoftPool + fold glob into conv4 bias
    softpool_kernel<<<512, 256, SPSM>>>(w9, b9);
    bias4_kernel<<<32, 256>>>(w4, b4);

    // L4: 64 -> 512 (2-term: post-softpool, smooth path)
    hmma_gemm_kernel<false><<<dim3(8, 2048), blk, SMEM2>>>(w4 + 32, 96, bias4p, 1, y1, 64, 0, y4, 512);
    finalize3_kernel<<<512, 256>>>(g4, be4, 3);

    // L5: 512 -> 256 (2-term)
    hmma_gemm_kernel<false><<<dim3(4, 2048), blk, SMEM2>>>(w5, 512, b5, 0, y4, 512, 3, y5, 256);
    finalize3_kernel<<<256, 256>>>(g5, be5, 4);

    // L6: 256 -> 128 (2-term: post-softpool, smooth path)
    hmma_gemm_kernel<false><<<dim3(2, 2048), blk, SMEM2>>>(w6, 256, b6, 0, y5, 256, 4, y6, 128);
    finalize3_kernel<<<128, 256>>>(g6, be6, 5);

    // L7: 128 -> 3, tanh, dedicated kernel, straight to output
    conv7_kernel<<<BNTOT/4/256, blk>>>(w7, b7, y6, (float*)d_out);
}

// round 14
// speedup vs baseline: 1.2313x; 1.0579x over previous
#include <cuda_runtime.h>
#include <cuda_fp16.h>
#include <math.h>
#include <stdint.h>

#define BATCH 16
#define NPTS  16384
#define BNTOT (BATCH*NPTS)
#define NTILE (BNTOT/256)   // 1024 column tiles (fp32 gemm path)
#define HPT   8192          // hmma stats partials per channel

typedef unsigned long long ull;

// ---------------- packed f32x2 / fp16 helpers --------------------------------
__device__ __forceinline__ ull pack2(float lo, float hi) {
    ull r; asm("mov.b64 %0, {%1, %2};" : "=l"(r) : "f"(lo), "f"(hi)); return r;
}
__device__ __forceinline__ ull fma2(ull a, ull b, ull c) {
    ull d; asm("fma.rn.f32x2 %0, %1, %2, %3;" : "=l"(d) : "l"(a), "l"(b), "l"(c)); return d;
}
__device__ __forceinline__ void unpack2(ull v, float& lo, float& hi) {
    asm("mov.b64 {%0, %1}, %2;" : "=f"(lo), "=f"(hi) : "l"(v));
}
__device__ __forceinline__ uint32_t cvt_h2(float lo, float hi) {
    uint32_t r;
    asm("cvt.rn.satfinite.f16x2.f32 %0, %1, %2;" : "=r"(r) : "f"(hi), "f"(lo));
    return r;
}
__device__ __forceinline__ float lo_h2(uint32_t h) {
    __half2 hh = *reinterpret_cast<const __half2*>(&h);
    return __low2float(hh);
}
__device__ __forceinline__ float hi_h2(uint32_t h) {
    __half2 hh = *reinterpret_cast<const __half2*>(&h);
    return __high2float(hh);
}
__device__ __forceinline__ void mma_f16(float d[4], const uint32_t a[4], const uint32_t b[2]) {
    asm volatile("mma.sync.aligned.m16n8k16.row.col.f32.f16.f16.f32 "
        "{%0,%1,%2,%3}, {%4,%5,%6,%7}, {%8,%9}, {%0,%1,%2,%3};"
        : "+f"(d[0]), "+f"(d[1]), "+f"(d[2]), "+f"(d[3])
        : "r"(a[0]), "r"(a[1]), "r"(a[2]), "r"(a[3]), "r"(b[0]), "r"(b[1]));
}
// canonical A-fragment load: 16x16 f16 tile, rows contiguous in smem
__device__ __forceinline__ void ldsm_x4(uint32_t r[4], const uint32_t* p) {
    uint32_t a = (uint32_t)__cvta_generic_to_shared(p);
    asm volatile("ldmatrix.sync.aligned.m8n8.x4.shared.b16 {%0,%1,%2,%3}, [%4];"
        : "=r"(r[0]), "=r"(r[1]), "=r"(r[2]), "=r"(r[3]) : "r"(a));
}

// ---------------- scratch (device globals) ----------------------------------
__device__ float g_y1[(size_t)BATCH*64*NPTS];
__device__ float g_y2[(size_t)BATCH*128*NPTS];
__device__ float g_y3[(size_t)BATCH*32*NPTS];
__device__ float g_y4[(size_t)BATCH*512*NPTS];
__device__ float g_y5[(size_t)BATCH*256*NPTS];
__device__ float g_y6[(size_t)BATCH*128*NPTS];
__device__ float g_bsum[(size_t)64*NTILE];      // L1 fused stats [c][tile]
__device__ float g_bsq [(size_t)64*NTILE];
__device__ float g_hsum[(size_t)512*HPT];       // hmma fused stats [c][tile*4+warpN]
__device__ float g_hsq [(size_t)512*HPT];
__device__ float g_scale[6][512];
__device__ float g_shift[6][512];
__device__ float g_v[BATCH*32];
__device__ float g_bias4[BATCH*512];

// =================== HMMA fp16 split GEMM (layers 2-6) =======================
// TERMS=3: A=[wh|wl], B=[xh|xl]; D = wh*xh + wh*xl + wl*xh  (~2e-6)
//          -- layers feeding the softpool argsort (L2,L3).
// TERMS=2: A=[wh|wl], B=x16;     D = wh*x + wl*x            (~3e-4/layer)
//          -- post-softpool smooth layers (L4,L6).
// TERMS=1: A=wh,      B=x16;     D = w16*x16                (~4.2e-4/layer)
//          -- L5 only (63% of MACs, smooth path, biggest win per error spent).
#define A_STR   36               // 32 data words + 4 pad
#define B_STR   136              // 128 data words + 8 pad
#define B0_W    2304             // A region = 64*36 words
#define SBUF3_W 6656             // A + B(32 rows)  -- TERMS=3 buffer words
#define SBUF2_W 4480             // A + B(16 rows)  -- TERMS<=2 buffer words

template<int TERMS>
__global__ void __launch_bounds__(256, 2)
hmma_gemm_kernel(const float* __restrict__ W, int wstride,
                 const float* __restrict__ bias, int biasPerBatch,
                 const float* __restrict__ X, int Ci, int inLayer,
                 float* __restrict__ Y, int Co)
{
    extern __shared__ uint32_t sm[];
    constexpr int SBUF_W = (TERMS == 3) ? SBUF3_W : SBUF2_W;
    const int t    = threadIdx.x;
    const int lane = t & 31, wid = t >> 5;
    const int warpM = wid & 1, warpN = wid >> 1;   // 2 x 4 warps, warp tile 32x32
    const int l4 = lane >> 2, q = lane & 3;
    const int b   = blockIdx.y >> 7;
    const int n0  = (blockIdx.y & 127) * 128;
    const int co0 = blockIdx.x * 64;

    const float* __restrict__ scv = g_scale[inLayer];
    const float* __restrict__ shv = g_shift[inLayer];
    const int nChunks = Ci >> 5;

    float acc[2][4][4];
#pragma unroll
    for (int mt = 0; mt < 2; mt++)
#pragma unroll
        for (int nt = 0; nt < 4; nt++)
#pragma unroll
            for (int j = 0; j < 4; j++) acc[mt][nt][j] = 0.f;

    // register staging for the in-flight chunk
    float4 aw[2];           // weights
    float4 bx0[2], bx1[2];  // activations (channel pair)

    auto ldg_chunk = [&](int ci0) {
#pragma unroll
        for (int i = 0; i < 2; i++) {
            int slot = i*256 + t;
            int co = slot >> 3, f4 = slot & 7;
            int cog = co0 + co;
            aw[i] = (cog < Co) ? *(const float4*)&W[(size_t)cog*wstride + ci0 + f4*4]
                               : make_float4(0.f, 0.f, 0.f, 0.f);
        }
#pragma unroll
        for (int i = 0; i < 2; i++) {
            int slot = i*256 + t;
            int kp = slot >> 5, f4 = slot & 31;
            int c0 = ci0 + kp*2;
            bx0[i] = *(const float4*)&X[((size_t)b*Ci + c0  )*NPTS + n0 + f4*4];
            bx1[i] = *(const float4*)&X[((size_t)b*Ci + c0+1)*NPTS + n0 + f4*4];
        }
    };

    auto sts_chunk = [&](int bufW, int ci0) {
        // A: wh always; wl when TERMS >= 2
#pragma unroll
        for (int i = 0; i < 2; i++) {
            int slot = i*256 + t;
            int co = slot >> 3, f4 = slot & 7;
            float4 w = aw[i];
            uint32_t h0 = cvt_h2(w.x, w.y);
            uint32_t h1 = cvt_h2(w.z, w.w);
            int wi = bufW + co*A_STR + f4*2;
            *(uint2*)&sm[wi] = make_uint2(h0, h1);        // wh
            if (TERMS >= 2) {
                uint32_t l0 = cvt_h2(w.x - lo_h2(h0), w.y - hi_h2(h0));
                uint32_t l1 = cvt_h2(w.z - lo_h2(h1), w.w - hi_h2(h1));
                *(uint2*)&sm[wi + 16] = make_uint2(l0, l1);   // wl
            }
        }
        // B: TERMS==3 -> [xh | xl]; else x16 only.  BN+ReLU fused.
#pragma unroll
        for (int i = 0; i < 2; i++) {
            int slot = i*256 + t;
            int kp = slot >> 5, f4 = slot & 31;
            int c0 = ci0 + kp*2;
            float s0 = scv[c0],   h0s = shv[c0];
            float s1 = scv[c0+1], h1s = shv[c0+1];
            float x0[4] = {bx0[i].x, bx0[i].y, bx0[i].z, bx0[i].w};
            float x1[4] = {bx1[i].x, bx1[i].y, bx1[i].z, bx1[i].w};
            uint32_t hw[4], lw[4];
#pragma unroll
            for (int j = 0; j < 4; j++) {
                float a0 = fmaxf(fmaf(x0[j], s0, h0s), 0.f);
                float a1 = fmaxf(fmaf(x1[j], s1, h1s), 0.f);
                uint32_t h = cvt_h2(a0, a1);
                hw[j] = h;
                if (TERMS == 3) lw[j] = cvt_h2(a0 - lo_h2(h), a1 - hi_h2(h));
            }
            int wi = bufW + B0_W + kp*B_STR + f4*4;
            *(uint4*)&sm[wi] = make_uint4(hw[0], hw[1], hw[2], hw[3]);            // xh / x16
            if (TERMS == 3)
                *(uint4*)&sm[wi + 16*B_STR] = make_uint4(lw[0], lw[1], lw[2], lw[3]); // xl
        }
    };

    ldg_chunk(0);   // prologue

    // ldmatrix addressing (constant per thread)
    const int lrow = lane & 15;
    const int lkw  = (lane >> 4) * 4;

    for (int c = 0; c < nChunks; c++) {
        const int bufW = (c & 1) * SBUF_W;
        sts_chunk(bufW, c << 5);
        __syncthreads();                         // STS(c) visible to all warps
        if (c + 1 < nChunks) ldg_chunk((c+1) << 5);   // latency hidden by compute

        const uint32_t* Aw = sm + bufW;
        const uint32_t* Bx = sm + bufW + B0_W;

#pragma unroll
        for (int kg = 0; kg < 2; kg++) {         // k16 group within the chunk
            uint32_t ah[2][4], al[2][4];
#pragma unroll
            for (int mt = 0; mt < 2; mt++) {
                const uint32_t* base =
                    Aw + (warpM*32 + mt*16 + lrow) * A_STR + kg*8 + lkw;
                ldsm_x4(ah[mt], base);           // wh fragment
                if (TERMS >= 2) ldsm_x4(al[mt], base + 16);   // wl fragment
            }
            uint32_t bh[4][2], bl[4][2];
#pragma unroll
            for (int nt = 0; nt < 4; nt++) {
                int base = (kg*8 + q) * B_STR + warpN*32 + nt*8 + l4;
                bh[nt][0] = Bx[base];             bh[nt][1] = Bx[base + 4*B_STR];
                if (TERMS == 3) {
                    bl[nt][0] = Bx[base + 16*B_STR];  bl[nt][1] = Bx[base + 20*B_STR];
                }
            }
#pragma unroll
            for (int mt = 0; mt < 2; mt++)
#pragma unroll
                for (int nt = 0; nt < 4; nt++) {
                    mma_f16(acc[mt][nt], ah[mt], bh[nt]);             // wh * x
                    if (TERMS == 3) {
                        mma_f16(acc[mt][nt], ah[mt], bl[nt]);         // wh * xl
                        mma_f16(acc[mt][nt], al[mt], bh[nt]);         // wl * xh
                    } else if (TERMS == 2) {
                        mma_f16(acc[mt][nt], al[mt], bh[nt]);         // wl * x
                    }
                }
        }
    }

    // ---- epilogue: store Y + fused per-row stats partials ----
    const int tileIdx = blockIdx.y * 4 + warpN;
#pragma unroll
    for (int mt = 0; mt < 2; mt++) {
        int row0 = co0 + warpM*32 + mt*16 + l4;
        int row1 = row0 + 8;
        float bs0 = 0.f, bs1 = 0.f;
        if (row0 < Co) bs0 = biasPerBatch ? bias[(size_t)b*Co + row0] : bias[row0];
        if (row1 < Co) bs1 = biasPerBatch ? bias[(size_t)b*Co + row1] : bias[row1];
        float s0 = 0.f, q0 = 0.f, s1 = 0.f, q1 = 0.f;
#pragma unroll
        for (int nt = 0; nt < 4; nt++) {
            int col = n0 + warpN*32 + nt*8 + q*2;
            float o0 = acc[mt][nt][0] + bs0, o1 = acc[mt][nt][1] + bs0;
            float o2 = acc[mt][nt][2] + bs1, o3 = acc[mt][nt][3] + bs1;
            s0 += o0 + o1;  q0 = fmaf(o0, o0, q0); q0 = fmaf(o1, o1, q0);
            s1 += o2 + o3;  q1 = fmaf(o2, o2, q1); q1 = fmaf(o3, o3, q1);
            if (row0 < Co)
                *(float2*)&Y[((size_t)b*Co + row0)*NPTS + col] = make_float2(o0, o1);
            if (row1 < Co)
                *(float2*)&Y[((size_t)b*Co + row1)*NPTS + col] = make_float2(o2, o3);
        }
        s0 += __shfl_xor_sync(0xffffffffu, s0, 1);  s0 += __shfl_xor_sync(0xffffffffu, s0, 2);
        q0 += __shfl_xor_sync(0xffffffffu, q0, 1);  q0 += __shfl_xor_sync(0xffffffffu, q0, 2);
        s1 += __shfl_xor_sync(0xffffffffu, s1, 1);  s1 += __shfl_xor_sync(0xffffffffu, s1, 2);
        q1 += __shfl_xor_sync(0xffffffffu, q1, 1);  q1 += __shfl_xor_sync(0xffffffffu, q1, 2);
        if (q == 0) {
            if (row0 < Co) {
                g_hsum[(size_t)row0*HPT + tileIdx] = s0;
                g_hsq [(size_t)row0*HPT + tileIdx] = q0;
            }
            if (row1 < Co) {
                g_hsum[(size_t)row1*HPT + tileIdx] = s1;
                g_hsq [(size_t)row1*HPT + tileIdx] = q1;
            }
        }
    }
}

// ---------------- finalize3: reduce HPT partials -> BN scale/shift ----------
__global__ void __launch_bounds__(256)
finalize3_kernel(const float* __restrict__ gamma,
                 const float* __restrict__ beta, int layer)
{
    const int c = blockIdx.x;
    const int t = threadIdx.x;
    float s = 0.f, q = 0.f;
#pragma unroll
    for (int i = 0; i < HPT/256; i++) {
        s += g_hsum[(size_t)c * HPT + i*256 + t];
        q += g_hsq [(size_t)c * HPT + i*256 + t];
    }
    __shared__ float ss[256], sq[256];
    ss[t] = s; sq[t] = q;
    __syncthreads();
    for (int st = 128; st > 0; st >>= 1) {
        if (t < st) { ss[t] += ss[t + st]; sq[t] += sq[t + st]; }
        __syncthreads();
    }
    if (t == 0) {
        float m   = ss[0] * (1.0f / BNTOT);
        float var = sq[0] * (1.0f / BNTOT) - m * m;
        float rstd = rsqrtf(var + 1e-5f);
        float scl  = gamma[c] * rstd;
        g_scale[layer][c] = scl;
        g_shift[layer][c] = fmaf(-m, scl, beta[c]);
    }
}

// =================== fp32 FFMA2 GEMM (layer 1 only) ==========================
__global__ void __launch_bounds__(256, 2)
gemm_kernel(const float* __restrict__ W, int wstride,
            const float* __restrict__ bias,
            const float* __restrict__ X, int Ci,
            float* __restrict__ Y, int Co)
{
    __shared__ __align__(16) ull   As2[16][65];
    __shared__ __align__(16) float Xs[16][256];

    const int t  = threadIdx.x;
    const int tn = t & 15;
    const int r  = t >> 4;
    const int tilesPerBatch = NPTS / 256;
    const int b   = blockIdx.y / tilesPerBatch;
    const int n0  = (blockIdx.y % tilesPerBatch) * 256;
    const int co0 = blockIdx.x * 64;

    ull acc2[4][8];
#pragma unroll
    for (int j = 0; j < 4; j++)
#pragma unroll
        for (int qq = 0; qq < 8; qq++) acc2[j][qq] = 0ull;

    const int nChunks = (Ci + 15) >> 4;
    float  wreg[4];
    float4 xreg[4];

    {
#pragma unroll
        for (int i = 0; i < 4; i++) {
            int lin = i*256 + t;
            int k = lin & 15, co = lin >> 4;
            int ci = k, cog = co0 + co;
            wreg[i] = (ci < Ci && cog < Co) ? W[(size_t)cog * wstride + ci] : 0.f;
        }
#pragma unroll
        for (int i = 0; i < 4; i++) {
            int fidx = i*256 + t;
            int k  = fidx >> 6;
            int n4 = fidx & 63;
            xreg[i] = (k < Ci) ? *(const float4*)&X[((size_t)b * Ci + k) * NPTS + n0 + n4*4]
                               : make_float4(0.f,0.f,0.f,0.f);
        }
    }

    for (int c = 0; c < nChunks; c++) {
        const int k0 = c << 4;
        if (c > 0) __syncthreads();
#pragma unroll
        for (int i = 0; i < 4; i++) {
            int lin = i*256 + t;
            int k = lin & 15, co = lin >> 4;
            float w = wreg[i];
            As2[k][co] = pack2(w, w);
        }
#pragma unroll
        for (int i = 0; i < 4; i++) {
            int fidx = i*256 + t;
            int k  = fidx >> 6;
            int n4 = fidx & 63;
            *(float4*)&Xs[k][n4*4] = xreg[i];
        }
        __syncthreads();

        if (c + 1 < nChunks) {
            const int k0n = k0 + 16;
#pragma unroll
            for (int i = 0; i < 4; i++) {
                int lin = i*256 + t;
                int k = lin & 15, co = lin >> 4;
                int ci = k0n + k, cog = co0 + co;
                wreg[i] = (ci < Ci && cog < Co) ? W[(size_t)cog * wstride + ci] : 0.f;
            }
#pragma unroll
            for (int i = 0; i < 4; i++) {
                int fidx = i*256 + t;
                int k  = fidx >> 6;
                int n4 = fidx & 63;
                int ci = k0n + k;
                xreg[i] = (ci < Ci) ? *(const float4*)&X[((size_t)b * Ci + ci) * NPTS + n0 + n4*4]
                                    : make_float4(0.f,0.f,0.f,0.f);
            }
        }

#pragma unroll
        for (int kk = 0; kk < 16; kk++) {
            ull a0 = As2[kk][r*4 + 0];
            ull a1 = As2[kk][r*4 + 1];
            ull a2 = As2[kk][r*4 + 2];
            ull a3 = As2[kk][r*4 + 3];
#pragma unroll
            for (int g = 0; g < 4; g++) {
                ulonglong2 xv = *(const ulonglong2*)&Xs[kk][g*64 + tn*4];
                acc2[0][g*2+0] = fma2(a0, xv.x, acc2[0][g*2+0]);
                acc2[0][g*2+1] = fma2(a0, xv.y, acc2[0][g*2+1]);
                acc2[1][g*2+0] = fma2(a1, xv.x, acc2[1][g*2+0]);
                acc2[1][g*2+1] = fma2(a1, xv.y, acc2[1][g*2+1]);
                acc2[2][g*2+0] = fma2(a2, xv.x, acc2[2][g*2+0]);
                acc2[2][g*2+1] = fma2(a2, xv.y, acc2[2][g*2+1]);
                acc2[3][g*2+0] = fma2(a3, xv.x, acc2[3][g*2+0]);
                acc2[3][g*2+1] = fma2(a3, xv.y, acc2[3][g*2+1]);
            }
        }
    }

    const int tile = blockIdx.y;
#pragma unroll
    for (int j = 0; j < 4; j++) {
        int cog = co0 + r*4 + j;
        bool valid = (cog < Co);
        float bs = valid ? bias[cog] : 0.f;
        float s = 0.f, q = 0.f;
        float* yr = valid ? &Y[((size_t)b * Co + cog) * NPTS + n0] : (float*)0;
#pragma unroll
        for (int g = 0; g < 4; g++) {
            float4 o;
            unpack2(acc2[j][g*2+0], o.x, o.y);
            unpack2(acc2[j][g*2+1], o.z, o.w);
            o.x += bs; o.y += bs; o.z += bs; o.w += bs;
            s += (o.x + o.y) + (o.z + o.w);
            q = fmaf(o.x, o.x, q); q = fmaf(o.y, o.y, q);
            q = fmaf(o.z, o.z, q); q = fmaf(o.w, o.w, q);
            if (valid) *(float4*)&yr[g*64 + tn*4] = o;
        }
#pragma unroll
        for (int off = 8; off; off >>= 1) {
            s += __shfl_down_sync(0xffffffffu, s, off, 16);
            q += __shfl_down_sync(0xffffffffu, q, off, 16);
        }
        if (tn == 0 && valid) {
            g_bsum[(size_t)cog * NTILE + tile] = s;
            g_bsq [(size_t)cog * NTILE + tile] = q;
        }
    }
}

// ---------------- finalize for L1 ([c][NTILE]) -------------------------------
__global__ void __launch_bounds__(256)
finalize_kernel(const float* __restrict__ gamma,
                const float* __restrict__ beta, int layer)
{
    const int c = blockIdx.x;
    const int t = threadIdx.x;
    float s = 0.f, q = 0.f;
#pragma unroll
    for (int i = 0; i < NTILE/256; i++) {
        s += g_bsum[(size_t)c * NTILE + i*256 + t];
        q += g_bsq [(size_t)c * NTILE + i*256 + t];
    }
    __shared__ float ss[256], sq[256];
    ss[t] = s; sq[t] = q;
    __syncthreads();
    for (int st = 128; st > 0; st >>= 1) {
        if (t < st) { ss[t] += ss[t + st]; sq[t] += sq[t + st]; }
        __syncthreads();
    }
    if (t == 0) {
        float m   = ss[0] * (1.0f / BNTOT);
        float var = sq[0] * (1.0f / BNTOT) - m * m;
        float rstd = rsqrtf(var + 1e-5f);
        float scl  = gamma[c] * rstd;
        g_scale[layer][c] = scl;
        g_shift[layer][c] = fmaf(-m, scl, beta[c]);
    }
}

// ---------------- dedicated L7: 128 -> 3, tanh ------------------------------
__global__ void __launch_bounds__(256)
conv7_kernel(const float* __restrict__ w7, const float* __restrict__ b7,
             const float* __restrict__ Y6, float* __restrict__ out)
{
    __shared__ float sw0[128], sw1[128], sw2[128], ssc[128], ssh[128];
    const int t = threadIdx.x;
    if (t < 128) {
        sw0[t] = w7[t]; sw1[t] = w7[128 + t]; sw2[t] = w7[256 + t];
        ssc[t] = g_scale[5][t]; ssh[t] = g_shift[5][t];
    }
    __syncthreads();

    const int idx = blockIdx.x * 256 + t;        // 65536 threads, 4 pts each
    const int b = idx >> 12;
    const int n = (idx & 4095) * 4;

    float4 a0 = make_float4(0.f,0.f,0.f,0.f);
    float4 a1 = a0, a2 = a0;
#pragma unroll 4
    for (int c = 0; c < 128; c++) {
        float4 v = *(const float4*)&Y6[((size_t)b*128 + c)*NPTS + n];
        float s = ssc[c], h = ssh[c];
        v.x = fmaxf(fmaf(v.x, s, h), 0.f);
        v.y = fmaxf(fmaf(v.y, s, h), 0.f);
        v.z = fmaxf(fmaf(v.z, s, h), 0.f);
        v.w = fmaxf(fmaf(v.w, s, h), 0.f);
        float w0 = sw0[c], w1 = sw1[c], w2 = sw2[c];
        a0.x = fmaf(w0, v.x, a0.x); a0.y = fmaf(w0, v.y, a0.y);
        a0.z = fmaf(w0, v.z, a0.z); a0.w = fmaf(w0, v.w, a0.w);
        a1.x = fmaf(w1, v.x, a1.x); a1.y = fmaf(w1, v.y, a1.y);
        a1.z = fmaf(w1, v.z, a1.z); a1.w = fmaf(w1, v.w, a1.w);
        a2.x = fmaf(w2, v.x, a2.x); a2.y = fmaf(w2, v.y, a2.y);
        a2.z = fmaf(w2, v.z, a2.z); a2.w = fmaf(w2, v.w, a2.w);
    }
    float b0 = b7[0], b1 = b7[1], b2 = b7[2];
    float4 o0 = make_float4(tanhf(a0.x+b0), tanhf(a0.y+b0), tanhf(a0.z+b0), tanhf(a0.w+b0));
    float4 o1 = make_float4(tanhf(a1.x+b1), tanhf(a1.y+b1), tanhf(a1.z+b1), tanhf(a1.w+b1));
    float4 o2 = make_float4(tanhf(a2.x+b2), tanhf(a2.y+b2), tanhf(a2.z+b2), tanhf(a2.w+b2));
    *(float4*)&out[((size_t)b*3 + 0)*NPTS + n] = o0;
    *(float4*)&out[((size_t)b*3 + 1)*NPTS + n] = o1;
    *(float4*)&out[((size_t)b*3 + 2)*NPTS + n] = o2;
}

// ---------------- SoftPool with smem row cache -------------------------------
__global__ void __launch_bounds__(256)
softpool_kernel(const float* __restrict__ w9, const float* __restrict__ b9)
{
    extern __shared__ float cache[];   // 16384 floats (64 KB)
    const int b = blockIdx.x >> 5;
    const int k = blockIdx.x & 31;
    const int t = threadIdx.x;

    __shared__ float sVal[256];
    __shared__ int   sIdx[256];
    __shared__ int   selIdx[16];

    const float sc = g_scale[2][k], sh = g_shift[2][k];
    const float* __restrict__ row = &g_y3[((size_t)b * 32 + k) * NPTS];

    for (int n = t; n < NPTS; n += 256) cache[n] = fmaf(row[n], sc, sh);
    __syncthreads();

    float lastV = -3.402823466e38f;
    int   lastI = -1;

    for (int p = 0; p < 16; p++) {
        float bv = 3.402823466e38f;
        int   bi = NPTS;
        for (int n = t; n < NPTS; n += 256) {
            float val = cache[n];
            bool elig = (val > lastV) || (val == lastV && n > lastI);
            if (elig && (val < bv || (val == bv && n < bi))) { bv = val; bi = n; }
        }
        sVal[t] = bv; sIdx[t] = bi;
        __syncthreads();
        for (int st = 128; st > 0; st >>= 1) {
            if (t < st) {
                float ov = sVal[t + st]; int oi = sIdx[t + st];
                if (ov < sVal[t] || (ov == sVal[t] && oi < sIdx[t])) { sVal[t] = ov; sIdx[t] = oi; }
            }
            __syncthreads();
        }
        lastV = sVal[0]; lastI = sIdx[0];
        if (t == 0) selIdx[p] = sIdx[0];
        __syncthreads();
    }

    float part = 0.f;
    for (int i = t; i < 512; i += 256) {
        int c = i >> 4, p = i & 15;
        int n = selIdx[p];
        float val = fmaf(g_y3[((size_t)b * 32 + c) * NPTS + n], g_scale[2][c], g_shift[2][c]);
        part = fmaf(w9[c * 16 + p], val, part);
    }
    sVal[t] = part;
    __syncthreads();
    for (int st = 128; st > 0; st >>= 1) {
        if (t < st) sVal[t] += sVal[t + st];
        __syncthreads();
    }
    if (t == 0) g_v[b * 32 + k] = sVal[0] + b9[0];
}

// ---------------- fold glob into conv4 bias ---------------------------------
__global__ void bias4_kernel(const float* __restrict__ w4, const float* __restrict__ b4)
{
    int idx = blockIdx.x * 256 + threadIdx.x;
    if (idx >= BATCH * 512) return;
    int b = idx >> 9, co = idx & 511;
    float s = b4[co];
#pragma unroll
    for (int k = 0; k < 32; k++) s = fmaf(w4[co * 96 + k], g_v[b * 32 + k], s);
    g_bias4[idx] = s;
}

// ---------------------------------------------------------------------------
extern "C" void kernel_launch(void* const* d_in, const int* in_sizes, int n_in,
                              void* d_out, int out_size)
{
    const float* x   = (const float*)d_in[0];
    const float* w1  = (const float*)d_in[1];  const float* b1  = (const float*)d_in[2];
    const float* g1  = (const float*)d_in[3];  const float* be1 = (const float*)d_in[4];
    const float* w2  = (const float*)d_in[5];  const float* b2  = (const float*)d_in[6];
    const float* g2  = (const float*)d_in[7];  const float* be2 = (const float*)d_in[8];
    const float* w3  = (const float*)d_in[9];  const float* b3  = (const float*)d_in[10];
    const float* g3  = (const float*)d_in[11]; const float* be3 = (const float*)d_in[12];
    const float* w9  = (const float*)d_in[13]; const float* b9  = (const float*)d_in[14];
    const float* w4  = (const float*)d_in[15]; const float* b4  = (const float*)d_in[16];
    const float* g4  = (const float*)d_in[17]; const float* be4 = (const float*)d_in[18];
    const float* w5  = (const float*)d_in[19]; const float* b5  = (const float*)d_in[20];
    const float* g5  = (const float*)d_in[21]; const float* be5 = (const float*)d_in[22];
    const float* w6  = (const float*)d_in[23]; const float* b6  = (const float*)d_in[24];
    const float* g6  = (const float*)d_in[25]; const float* be6 = (const float*)d_in[26];
    const float* w7  = (const float*)d_in[27]; const float* b7  = (const float*)d_in[28];

    float *y1, *y2, *y3, *y4, *y5, *y6, *bias4p;
    cudaGetSymbolAddress((void**)&y1, g_y1);
    cudaGetSymbolAddress((void**)&y2, g_y2);
    cudaGetSymbolAddress((void**)&y3, g_y3);
    cudaGetSymbolAddress((void**)&y4, g_y4);
    cudaGetSymbolAddress((void**)&y5, g_y5);
    cudaGetSymbolAddress((void**)&y6, g_y6);
    cudaGetSymbolAddress((void**)&bias4p, g_bias4);

    const int SMEM3 = 2 * SBUF3_W * 4;   // 53248 B
    const int SMEM2 = 2 * SBUF2_W * 4;   // 35840 B
    cudaFuncSetAttribute(hmma_gemm_kernel<3>, cudaFuncAttributeMaxDynamicSharedMemorySize, SMEM3);
    cudaFuncSetAttribute(hmma_gemm_kernel<2>, cudaFuncAttributeMaxDynamicSharedMemorySize, SMEM2);
    cudaFuncSetAttribute(hmma_gemm_kernel<1>, cudaFuncAttributeMaxDynamicSharedMemorySize, SMEM2);
    const int SPSM = NPTS * 4;           // 65536 B
    cudaFuncSetAttribute(softpool_kernel, cudaFuncAttributeMaxDynamicSharedMemorySize, SPSM);

    const dim3 blk(256);

    // L1: 4 -> 64 (fp32, fused stats)
    gemm_kernel<<<dim3(1, NTILE), blk>>>(w1, 4, b1, x, 4, y1, 64);
    finalize_kernel<<<64, 256>>>(g1, be1, 0);

    // L2: 64 -> 128 (3-term: feeds softpool selection)
    hmma_gemm_kernel<3><<<dim3(2, 2048), blk, SMEM3>>>(w2, 64, b2, 0, y1, 64, 0, y2, 128);
    finalize3_kernel<<<128, 256>>>(g2, be2, 1);

    // L3: 128 -> 32 (3-term: feeds softpool selection)
    hmma_gemm_kernel<3><<<dim3(1, 2048), blk, SMEM3>>>(w3, 128, b3, 0, y2, 128, 1, y3, 32);
    finalize3_kernel<<<32, 256>>>(g3, be3, 2);

    // SoftPool + fold glob into conv4 bias
    softpool_kernel<<<512, 256, SPSM>>>(w9, b9);
    bias4_kernel<<<32, 256>>>(w4, b4);

    // L4: 64 -> 512 (2-term: post-softpool, smooth path)
    hmma_gemm_kernel<2><<<dim3(8, 2048), blk, SMEM2>>>(w4 + 32, 96, bias4p, 1, y1, 64, 0, y4, 512);
    finalize3_kernel<<<512, 256>>>(g4, be4, 3);

    // L5: 512 -> 256 (1-term: 63% of MACs, smooth path, both operands fp16)
    hmma_gemm_kernel<1><<<dim3(4, 2048), blk, SMEM2>>>(w5, 512, b5, 0, y4, 512, 3, y5, 256);
    finalize3_kernel<<<256, 256>>>(g5, be5, 4);

    // L6: 256 -> 128 (2-term)
    hmma_gemm_kernel<2><<<dim3(2, 2048), blk, SMEM2>>>(w6, 256, b6, 0, y5, 256, 4, y6, 128);
    finalize3_kernel<<<128, 256>>>(g6, be6, 5);

    // L7: 128 -> 3, tanh, dedicated kernel, straight to output
    conv7_kernel<<<BNTOT/4/256, blk>>>(w7, b7, y6, (float*)d_out);
}

// round 15
// speedup vs baseline: 1.2825x; 1.0416x over previous
#include <cuda_runtime.h>
#include <cuda_fp16.h>
#include <math.h>
#include <stdint.h>

#define BATCH 16
#define NPTS  16384
#define BNTOT (BATCH*NPTS)
#define NTILE (BNTOT/256)   // 1024 column tiles (fp32 gemm path)
#define HPT   8192          // hmma stats partials per channel

typedef unsigned long long ull;

// ---------------- packed f32x2 / fp16 helpers --------------------------------
__device__ __forceinline__ ull pack2(float lo, float hi) {
    ull r; asm("mov.b64 %0, {%1, %2};" : "=l"(r) : "f"(lo), "f"(hi)); return r;
}
__device__ __forceinline__ ull fma2(ull a, ull b, ull c) {
    ull d; asm("fma.rn.f32x2 %0, %1, %2, %3;" : "=l"(d) : "l"(a), "l"(b), "l"(c)); return d;
}
__device__ __forceinline__ void unpack2(ull v, float& lo, float& hi) {
    asm("mov.b64 {%0, %1}, %2;" : "=f"(lo), "=f"(hi) : "l"(v));
}
__device__ __forceinline__ uint32_t cvt_h2(float lo, float hi) {
    uint32_t r;
    asm("cvt.rn.satfinite.f16x2.f32 %0, %1, %2;" : "=r"(r) : "f"(hi), "f"(lo));
    return r;
}
__device__ __forceinline__ float lo_h2(uint32_t h) {
    __half2 hh = *reinterpret_cast<const __half2*>(&h);
    return __low2float(hh);
}
__device__ __forceinline__ float hi_h2(uint32_t h) {
    __half2 hh = *reinterpret_cast<const __half2*>(&h);
    return __high2float(hh);
}
__device__ __forceinline__ void mma_f16(float d[4], const uint32_t a[4], const uint32_t b[2]) {
    asm volatile("mma.sync.aligned.m16n8k16.row.col.f32.f16.f16.f32 "
        "{%0,%1,%2,%3}, {%4,%5,%6,%7}, {%8,%9}, {%0,%1,%2,%3};"
        : "+f"(d[0]), "+f"(d[1]), "+f"(d[2]), "+f"(d[3])
        : "r"(a[0]), "r"(a[1]), "r"(a[2]), "r"(a[3]), "r"(b[0]), "r"(b[1]));
}
// canonical A-fragment load: 16x16 f16 tile, rows contiguous in smem
__device__ __forceinline__ void ldsm_x4(uint32_t r[4], const uint32_t* p) {
    uint32_t a = (uint32_t)__cvta_generic_to_shared(p);
    asm volatile("ldmatrix.sync.aligned.m8n8.x4.shared.b16 {%0,%1,%2,%3}, [%4];"
        : "=r"(r[0]), "=r"(r[1]), "=r"(r[2]), "=r"(r[3]) : "r"(a));
}

// ---------------- scratch (device globals) ----------------------------------
__device__ float  g_y1[(size_t)BATCH*64*NPTS];
__device__ float  g_y2[(size_t)BATCH*128*NPTS];
__device__ float  g_y3[(size_t)BATCH*32*NPTS];
__device__ __half g_y4h[(size_t)BATCH*512*NPTS];   // fp16 activations (smooth path)
__device__ __half g_y5h[(size_t)BATCH*256*NPTS];
__device__ float  g_y6[(size_t)BATCH*128*NPTS];
__device__ float g_bsum[(size_t)64*NTILE];      // L1 fused stats [c][tile]
__device__ float g_bsq [(size_t)64*NTILE];
__device__ float g_hsum[(size_t)512*HPT];       // hmma fused stats [c][tile*4+warpN]
__device__ float g_hsq [(size_t)512*HPT];
__device__ float g_scale[6][512];
__device__ float g_shift[6][512];
__device__ float g_v[BATCH*32];
__device__ float g_bias4[BATCH*512];

// =================== HMMA fp16 split GEMM (layers 2-6) =======================
// TERMS=3: A=[wh|wl], B=[xh|xl]; D = wh*xh + wh*xl + wl*xh  (~2e-6)
// TERMS=2: A=[wh|wl], B=x16;     D = wh*x + wl*x            (~3e-4/layer)
// TERMS=1: A=wh,      B=x16;     D = w16*x16                (~4.2e-4/layer)
// INF16 : X is fp16 (pre-rounded activations; consumer rounds to fp16 anyway)
// OUTF16: Y stored as fp16 (halves DRAM traffic; stats still on fp32 acc)
#define A_STR   36               // 32 data words + 4 pad
#define B_STR   136              // 128 data words + 8 pad
#define B0_W    2304             // A region = 64*36 words
#define SBUF3_W 6656             // A + B(32 rows)  -- TERMS=3 buffer words
#define SBUF2_W 4480             // A + B(16 rows)  -- TERMS<=2 buffer words

template<int TERMS, bool INF16, bool OUTF16>
__global__ void __launch_bounds__(256, 2)
hmma_gemm_kernel(const float* __restrict__ W, int wstride,
                 const float* __restrict__ bias, int biasPerBatch,
                 const void* __restrict__ Xv, int Ci, int inLayer,
                 void* __restrict__ Yv, int Co)
{
    extern __shared__ uint32_t sm[];
    constexpr int SBUF_W = (TERMS == 3) ? SBUF3_W : SBUF2_W;
    const int t    = threadIdx.x;
    const int lane = t & 31, wid = t >> 5;
    const int warpM = wid & 1, warpN = wid >> 1;   // 2 x 4 warps, warp tile 32x32
    const int l4 = lane >> 2, q = lane & 3;
    const int b   = blockIdx.y >> 7;
    const int n0  = (blockIdx.y & 127) * 128;
    const int co0 = blockIdx.x * 64;

    const float*  __restrict__ Xf = (const float*)Xv;
    const __half* __restrict__ Xh = (const __half*)Xv;
    float*  __restrict__ Yf = (float*)Yv;
    __half* __restrict__ Yh = (__half*)Yv;

    const float* __restrict__ scv = g_scale[inLayer];
    const float* __restrict__ shv = g_shift[inLayer];
    const int nChunks = Ci >> 5;

    float acc[2][4][4];
#pragma unroll
    for (int mt = 0; mt < 2; mt++)
#pragma unroll
        for (int nt = 0; nt < 4; nt++)
#pragma unroll
            for (int j = 0; j < 4; j++) acc[mt][nt][j] = 0.f;

    // register staging for the in-flight chunk
    float4 aw[2];                 // weights
    float4 bx0[2], bx1[2];        // activations fp32 path (channel pair)
    uint4  beH, boH;              // activations fp16 path (even/odd channel rows)

    auto ldg_chunk = [&](int ci0) {
#pragma unroll
        for (int i = 0; i < 2; i++) {
            int slot = i*256 + t;
            int co = slot >> 3, f4 = slot & 7;
            int cog = co0 + co;
            aw[i] = (cog < Co) ? *(const float4*)&W[(size_t)cog*wstride + ci0 + f4*4]
                               : make_float4(0.f, 0.f, 0.f, 0.f);
        }
        if (INF16) {
            int kp = t >> 4, f8 = t & 15;
            int c0 = ci0 + kp*2;
            beH = *(const uint4*)&Xh[((size_t)b*Ci + c0  )*NPTS + n0 + f8*8];
            boH = *(const uint4*)&Xh[((size_t)b*Ci + c0+1)*NPTS + n0 + f8*8];
        } else {
#pragma unroll
            for (int i = 0; i < 2; i++) {
                int slot = i*256 + t;
                int kp = slot >> 5, f4 = slot & 31;
                int c0 = ci0 + kp*2;
                bx0[i] = *(const float4*)&Xf[((size_t)b*Ci + c0  )*NPTS + n0 + f4*4];
                bx1[i] = *(const float4*)&Xf[((size_t)b*Ci + c0+1)*NPTS + n0 + f4*4];
            }
        }
    };

    auto sts_chunk = [&](int bufW, int ci0) {
        // A: wh always; wl when TERMS >= 2
#pragma unroll
        for (int i = 0; i < 2; i++) {
            int slot = i*256 + t;
            int co = slot >> 3, f4 = slot & 7;
            float4 w = aw[i];
            uint32_t h0 = cvt_h2(w.x, w.y);
            uint32_t h1 = cvt_h2(w.z, w.w);
            int wi = bufW + co*A_STR + f4*2;
            *(uint2*)&sm[wi] = make_uint2(h0, h1);        // wh
            if (TERMS >= 2) {
                uint32_t l0 = cvt_h2(w.x - lo_h2(h0), w.y - hi_h2(h0));
                uint32_t l1 = cvt_h2(w.z - lo_h2(h1), w.w - hi_h2(h1));
                *(uint2*)&sm[wi + 16] = make_uint2(l0, l1);   // wl
            }
        }
        // B staging, BN+ReLU fused
        if (INF16) {
            int kp = t >> 4, f8 = t & 15;
            int c0 = ci0 + kp*2;
            float s0 = scv[c0],   h0s = shv[c0];
            float s1 = scv[c0+1], h1s = shv[c0+1];
            const uint32_t* ew = (const uint32_t*)&beH;
            const uint32_t* ow = (const uint32_t*)&boH;
            uint32_t pk[8];
#pragma unroll
            for (int j = 0; j < 4; j++) {
                float e0 = fmaxf(fmaf(lo_h2(ew[j]), s0, h0s), 0.f);
                float e1 = fmaxf(fmaf(hi_h2(ew[j]), s0, h0s), 0.f);
                float o0 = fmaxf(fmaf(lo_h2(ow[j]), s1, h1s), 0.f);
                float o1 = fmaxf(fmaf(hi_h2(ow[j]), s1, h1s), 0.f);
                pk[j*2+0] = cvt_h2(e0, o0);
                pk[j*2+1] = cvt_h2(e1, o1);
            }
            int wi = bufW + B0_W + kp*B_STR + f8*8;
            *(uint4*)&sm[wi]     = make_uint4(pk[0], pk[1], pk[2], pk[3]);
            *(uint4*)&sm[wi + 4] = make_uint4(pk[4], pk[5], pk[6], pk[7]);
        } else {
#pragma unroll
            for (int i = 0; i < 2; i++) {
                int slot = i*256 + t;
                int kp = slot >> 5, f4 = slot & 31;
                int c0 = ci0 + kp*2;
                float s0 = scv[c0],   h0s = shv[c0];
                float s1 = scv[c0+1], h1s = shv[c0+1];
                float x0[4] = {bx0[i].x, bx0[i].y, bx0[i].z, bx0[i].w};
                float x1[4] = {bx1[i].x, bx1[i].y, bx1[i].z, bx1[i].w};
                uint32_t hw[4], lw[4];
#pragma unroll
                for (int j = 0; j < 4; j++) {
                    float a0 = fmaxf(fmaf(x0[j], s0, h0s), 0.f);
                    float a1 = fmaxf(fmaf(x1[j], s1, h1s), 0.f);
                    uint32_t h = cvt_h2(a0, a1);
                    hw[j] = h;
                    if (TERMS == 3) lw[j] = cvt_h2(a0 - lo_h2(h), a1 - hi_h2(h));
                }
                int wi = bufW + B0_W + kp*B_STR + f4*4;
                *(uint4*)&sm[wi] = make_uint4(hw[0], hw[1], hw[2], hw[3]);            // xh / x16
                if (TERMS == 3)
                    *(uint4*)&sm[wi + 16*B_STR] = make_uint4(lw[0], lw[1], lw[2], lw[3]); // xl
            }
        }
    };

    ldg_chunk(0);   // prologue

    // ldmatrix addressing (constant per thread)
    const int lrow = lane & 15;
    const int lkw  = (lane >> 4) * 4;

    for (int c = 0; c < nChunks; c++) {
        const int bufW = (c & 1) * SBUF_W;
        sts_chunk(bufW, c << 5);
        __syncthreads();                         // STS(c) visible to all warps
        if (c + 1 < nChunks) ldg_chunk((c+1) << 5);   // latency hidden by compute

        const uint32_t* Aw = sm + bufW;
        const uint32_t* Bx = sm + bufW + B0_W;

#pragma unroll
        for (int kg = 0; kg < 2; kg++) {         // k16 group within the chunk
            uint32_t ah[2][4], al[2][4];
#pragma unroll
            for (int mt = 0; mt < 2; mt++) {
                const uint32_t* base =
                    Aw + (warpM*32 + mt*16 + lrow) * A_STR + kg*8 + lkw;
                ldsm_x4(ah[mt], base);           // wh fragment
                if (TERMS >= 2) ldsm_x4(al[mt], base + 16);   // wl fragment
            }
            uint32_t bh[4][2], bl[4][2];
#pragma unroll
            for (int nt = 0; nt < 4; nt++) {
                int base = (kg*8 + q) * B_STR + warpN*32 + nt*8 + l4;
                bh[nt][0] = Bx[base];             bh[nt][1] = Bx[base + 4*B_STR];
                if (TERMS == 3) {
                    bl[nt][0] = Bx[base + 16*B_STR];  bl[nt][1] = Bx[base + 20*B_STR];
                }
            }
#pragma unroll
            for (int mt = 0; mt < 2; mt++)
#pragma unroll
                for (int nt = 0; nt < 4; nt++) {
                    mma_f16(acc[mt][nt], ah[mt], bh[nt]);             // wh * x
                    if (TERMS == 3) {
                        mma_f16(acc[mt][nt], ah[mt], bl[nt]);         // wh * xl
                        mma_f16(acc[mt][nt], al[mt], bh[nt]);         // wl * xh
                    } else if (TERMS == 2) {
                        mma_f16(acc[mt][nt], al[mt], bh[nt]);         // wl * x
                    }
                }
        }
    }

    // ---- epilogue: store Y (+fused per-row stats partials) ----
    const int tileIdx = blockIdx.y * 4 + warpN;
#pragma unroll
    for (int mt = 0; mt < 2; mt++) {
        int row0 = co0 + warpM*32 + mt*16 + l4;
        int row1 = row0 + 8;
        float bs0 = 0.f, bs1 = 0.f;
        if (row0 < Co) bs0 = biasPerBatch ? bias[(size_t)b*Co + row0] : bias[row0];
        if (row1 < Co) bs1 = biasPerBatch ? bias[(size_t)b*Co + row1] : bias[row1];
        float s0 = 0.f, q0 = 0.f, s1 = 0.f, q1 = 0.f;
#pragma unroll
        for (int nt = 0; nt < 4; nt++) {
            int col = n0 + warpN*32 + nt*8 + q*2;
            float o0 = acc[mt][nt][0] + bs0, o1 = acc[mt][nt][1] + bs0;
            float o2 = acc[mt][nt][2] + bs1, o3 = acc[mt][nt][3] + bs1;
            s0 += o0 + o1;  q0 = fmaf(o0, o0, q0); q0 = fmaf(o1, o1, q0);
            s1 += o2 + o3;  q1 = fmaf(o2, o2, q1); q1 = fmaf(o3, o3, q1);
            if (OUTF16) {
                if (row0 < Co)
                    *(uint32_t*)&Yh[((size_t)b*Co + row0)*NPTS + col] = cvt_h2(o0, o1);
                if (row1 < Co)
                    *(uint32_t*)&Yh[((size_t)b*Co + row1)*NPTS + col] = cvt_h2(o2, o3);
            } else {
                if (row0 < Co)
                    *(float2*)&Yf[((size_t)b*Co + row0)*NPTS + col] = make_float2(o0, o1);
                if (row1 < Co)
                    *(float2*)&Yf[((size_t)b*Co + row1)*NPTS + col] = make_float2(o2, o3);
            }
        }
        s0 += __shfl_xor_sync(0xffffffffu, s0, 1);  s0 += __shfl_xor_sync(0xffffffffu, s0, 2);
        q0 += __shfl_xor_sync(0xffffffffu, q0, 1);  q0 += __shfl_xor_sync(0xffffffffu, q0, 2);
        s1 += __shfl_xor_sync(0xffffffffu, s1, 1);  s1 += __shfl_xor_sync(0xffffffffu, s1, 2);
        q1 += __shfl_xor_sync(0xffffffffu, q1, 1);  q1 += __shfl_xor_sync(0xffffffffu, q1, 2);
        if (q == 0) {
            if (row0 < Co) {
                g_hsum[(size_t)row0*HPT + tileIdx] = s0;
                g_hsq [(size_t)row0*HPT + tileIdx] = q0;
            }
            if (row1 < Co) {
                g_hsum[(size_t)row1*HPT + tileIdx] = s1;
                g_hsq [(size_t)row1*HPT + tileIdx] = q1;
            }
        }
    }
}

// ---------------- finalize3: reduce HPT partials -> BN scale/shift ----------
__global__ void __launch_bounds__(256)
finalize3_kernel(const float* __restrict__ gamma,
                 const float* __restrict__ beta, int layer)
{
    const int c = blockIdx.x;
    const int t = threadIdx.x;
    float s = 0.f, q = 0.f;
#pragma unroll
    for (int i = 0; i < HPT/256; i++) {
        s += g_hsum[(size_t)c * HPT + i*256 + t];
        q += g_hsq [(size_t)c * HPT + i*256 + t];
    }
    __shared__ float ss[256], sq[256];
    ss[t] = s; sq[t] = q;
    __syncthreads();
    for (int st = 128; st > 0; st >>= 1) {
        if (t < st) { ss[t] += ss[t + st]; sq[t] += sq[t + st]; }
        __syncthreads();
    }
    if (t == 0) {
        float m   = ss[0] * (1.0f / BNTOT);
        float var = sq[0] * (1.0f / BNTOT) - m * m;
        float rstd = rsqrtf(var + 1e-5f);
        float scl  = gamma[c] * rstd;
        g_scale[layer][c] = scl;
        g_shift[layer][c] = fmaf(-m, scl, beta[c]);
    }
}

// =================== fp32 FFMA2 GEMM (layer 1 only) ==========================
__global__ void __launch_bounds__(256, 2)
gemm_kernel(const float* __restrict__ W, int wstride,
            const float* __restrict__ bias,
            const float* __restrict__ X, int Ci,
            float* __restrict__ Y, int Co)
{
    __shared__ __align__(16) ull   As2[16][65];
    __shared__ __align__(16) float Xs[16][256];

    const int t  = threadIdx.x;
    const int tn = t & 15;
    const int r  = t >> 4;
    const int tilesPerBatch = NPTS / 256;
    const int b   = blockIdx.y / tilesPerBatch;
    const int n0  = (blockIdx.y % tilesPerBatch) * 256;
    const int co0 = blockIdx.x * 64;

    ull acc2[4][8];
#pragma unroll
    for (int j = 0; j < 4; j++)
#pragma unroll
        for (int qq = 0; qq < 8; qq++) acc2[j][qq] = 0ull;

    const int nChunks = (Ci + 15) >> 4;
    float  wreg[4];
    float4 xreg[4];

    {
#pragma unroll
        for (int i = 0; i < 4; i++) {
            int lin = i*256 + t;
            int k = lin & 15, co = lin >> 4;
            int ci = k, cog = co0 + co;
            wreg[i] = (ci < Ci && cog < Co) ? W[(size_t)cog * wstride + ci] : 0.f;
        }
#pragma unroll
        for (int i = 0; i < 4; i++) {
            int fidx = i*256 + t;
            int k  = fidx >> 6;
            int n4 = fidx & 63;
            xreg[i] = (k < Ci) ? *(const float4*)&X[((size_t)b * Ci + k) * NPTS + n0 + n4*4]
                               : make_float4(0.f,0.f,0.f,0.f);
        }
    }

    for (int c = 0; c < nChunks; c++) {
        const int k0 = c << 4;
        if (c > 0) __syncthreads();
#pragma unroll
        for (int i = 0; i < 4; i++) {
            int lin = i*256 + t;
            int k = lin & 15, co = lin >> 4;
            float w = wreg[i];
            As2[k][co] = pack2(w, w);
        }
#pragma unroll
        for (int i = 0; i < 4; i++) {
            int fidx = i*256 + t;
            int k  = fidx >> 6;
            int n4 = fidx & 63;
            *(float4*)&Xs[k][n4*4] = xreg[i];
        }
        __syncthreads();

        if (c + 1 < nChunks) {
            const int k0n = k0 + 16;
#pragma unroll
            for (int i = 0; i < 4; i++) {
                int lin = i*256 + t;
                int k = lin & 15, co = lin >> 4;
                int ci = k0n + k, cog = co0 + co;
                wreg[i] = (ci < Ci && cog < Co) ? W[(size_t)cog * wstride + ci] : 0.f;
            }
#pragma unroll
            for (int i = 0; i < 4; i++) {
                int fidx = i*256 + t;
                int k  = fidx >> 6;
                int n4 = fidx & 63;
                int ci = k0n + k;
                xreg[i] = (ci < Ci) ? *(const float4*)&X[((size_t)b * Ci + ci) * NPTS + n0 + n4*4]
                                    : make_float4(0.f,0.f,0.f,0.f);
            }
        }

#pragma unroll
        for (int kk = 0; kk < 16; kk++) {
            ull a0 = As2[kk][r*4 + 0];
            ull a1 = As2[kk][r*4 + 1];
            ull a2 = As2[kk][r*4 + 2];
            ull a3 = As2[kk][r*4 + 3];
#pragma unroll
            for (int g = 0; g < 4; g++) {
                ulonglong2 xv = *(const ulonglong2*)&Xs[kk][g*64 + tn*4];
                acc2[0][g*2+0] = fma2(a0, xv.x, acc2[0][g*2+0]);
                acc2[0][g*2+1] = fma2(a0, xv.y, acc2[0][g*2+1]);
                acc2[1][g*2+0] = fma2(a1, xv.x, acc2[1][g*2+0]);
                acc2[1][g*2+1] = fma2(a1, xv.y, acc2[1][g*2+1]);
                acc2[2][g*2+0] = fma2(a2, xv.x, acc2[2][g*2+0]);
                acc2[2][g*2+1] = fma2(a2, xv.y, acc2[2][g*2+1]);
                acc2[3][g*2+0] = fma2(a3, xv.x, acc2[3][g*2+0]);
                acc2[3][g*2+1] = fma2(a3, xv.y, acc2[3][g*2+1]);
            }
        }
    }

    const int tile = blockIdx.y;
#pragma unroll
    for (int j = 0; j < 4; j++) {
        int cog = co0 + r*4 + j;
        bool valid = (cog < Co);
        float bs = valid ? bias[cog] : 0.f;
        float s = 0.f, q = 0.f;
        float* yr = valid ? &Y[((size_t)b * Co + cog) * NPTS + n0] : (float*)0;
#pragma unroll
        for (int g = 0; g < 4; g++) {
            float4 o;
            unpack2(acc2[j][g*2+0], o.x, o.y);
            unpack2(acc2[j][g*2+1], o.z, o.w);
            o.x += bs; o.y += bs; o.z += bs; o.w += bs;
            s += (o.x + o.y) + (o.z + o.w);
            q = fmaf(o.x, o.x, q); q = fmaf(o.y, o.y, q);
            q = fmaf(o.z, o.z, q); q = fmaf(o.w, o.w, q);
            if (valid) *(float4*)&yr[g*64 + tn*4] = o;
        }
#pragma unroll
        for (int off = 8; off; off >>= 1) {
            s += __shfl_down_sync(0xffffffffu, s, off, 16);
            q += __shfl_down_sync(0xffffffffu, q, off, 16);
        }
        if (tn == 0 && valid) {
            g_bsum[(size_t)cog * NTILE + tile] = s;
            g_bsq [(size_t)cog * NTILE + tile] = q;
        }
    }
}

// ---------------- finalize for L1 ([c][NTILE]) -------------------------------
__global__ void __launch_bounds__(256)
finalize_kernel(const float* __restrict__ gamma,
                const float* __restrict__ beta, int layer)
{
    const int c = blockIdx.x;
    const int t = threadIdx.x;
    float s = 0.f, q = 0.f;
#pragma unroll
    for (int i = 0; i < NTILE/256; i++) {
        s += g_bsum[(size_t)c * NTILE + i*256 + t];
        q += g_bsq [(size_t)c * NTILE + i*256 + t];
    }
    __shared__ float ss[256], sq[256];
    ss[t] = s; sq[t] = q;
    __syncthreads();
    for (int st = 128; st > 0; st >>= 1) {
        if (t < st) { ss[t] += ss[t + st]; sq[t] += sq[t + st]; }
        __syncthreads();
    }
    if (t == 0) {
        float m   = ss[0] * (1.0f / BNTOT);
        float var = sq[0] * (1.0f / BNTOT) - m * m;
        float rstd = rsqrtf(var + 1e-5f);
        float scl  = gamma[c] * rstd;
        g_scale[layer][c] = scl;
        g_shift[layer][c] = fmaf(-m, scl, beta[c]);
    }
}

// ---------------- dedicated L7: 128 -> 3, tanh ------------------------------
__global__ void __launch_bounds__(256)
conv7_kernel(const float* __restrict__ w7, const float* __restrict__ b7,
             const float* __restrict__ Y6, float* __restrict__ out)
{
    __shared__ float sw0[128], sw1[128], sw2[128], ssc[128], ssh[128];
    const int t = threadIdx.x;
    if (t < 128) {
        sw0[t] = w7[t]; sw1[t] = w7[128 + t]; sw2[t] = w7[256 + t];
        ssc[t] = g_scale[5][t]; ssh[t] = g_shift[5][t];
    }
    __syncthreads();

    const int idx = blockIdx.x * 256 + t;        // 65536 threads, 4 pts each
    const int b = idx >> 12;
    const int n = (idx & 4095) * 4;

    float4 a0 = make_float4(0.f,0.f,0.f,0.f);
    float4 a1 = a0, a2 = a0;
#pragma unroll 4
    for (int c = 0; c < 128; c++) {
        float4 v = *(const float4*)&Y6[((size_t)b*128 + c)*NPTS + n];
        float s = ssc[c], h = ssh[c];
        v.x = fmaxf(fmaf(v.x, s, h), 0.f);
        v.y = fmaxf(fmaf(v.y, s, h), 0.f);
        v.z = fmaxf(fmaf(v.z, s, h), 0.f);
        v.w = fmaxf(fmaf(v.w, s, h), 0.f);
        float w0 = sw0[c], w1 = sw1[c], w2 = sw2[c];
        a0.x = fmaf(w0, v.x, a0.x); a0.y = fmaf(w0, v.y, a0.y);
        a0.z = fmaf(w0, v.z, a0.z); a0.w = fmaf(w0, v.w, a0.w);
        a1.x = fmaf(w1, v.x, a1.x); a1.y = fmaf(w1, v.y, a1.y);
        a1.z = fmaf(w1, v.z, a1.z); a1.w = fmaf(w1, v.w, a1.w);
        a2.x = fmaf(w2, v.x, a2.x); a2.y = fmaf(w2, v.y, a2.y);
        a2.z = fmaf(w2, v.z, a2.z); a2.w = fmaf(w2, v.w, a2.w);
    }
    float b0 = b7[0], b1 = b7[1], b2 = b7[2];
    float4 o0 = make_float4(tanhf(a0.x+b0), tanhf(a0.y+b0), tanhf(a0.z+b0), tanhf(a0.w+b0));
    float4 o1 = make_float4(tanhf(a1.x+b1), tanhf(a1.y+b1), tanhf(a1.z+b1), tanhf(a1.w+b1));
    float4 o2 = make_float4(tanhf(a2.x+b2), tanhf(a2.y+b2), tanhf(a2.z+b2), tanhf(a2.w+b2));
    *(float4*)&out[((size_t)b*3 + 0)*NPTS + n] = o0;
    *(float4*)&out[((size_t)b*3 + 1)*NPTS + n] = o1;
    *(float4*)&out[((size_t)b*3 + 2)*NPTS + n] = o2;
}

// ---------------- SoftPool with smem row cache -------------------------------
__global__ void __launch_bounds__(256)
softpool_kernel(const float* __restrict__ w9, const float* __restrict__ b9)
{
    extern __shared__ float cache[];   // 16384 floats (64 KB)
    const int b = blockIdx.x >> 5;
    const int k = blockIdx.x & 31;
    const int t = threadIdx.x;

    __shared__ float sVal[256];
    __shared__ int   sIdx[256];
    __shared__ int   selIdx[16];

    const float sc = g_scale[2][k], sh = g_shift[2][k];
    const float* __restrict__ row = &g_y3[((size_t)b * 32 + k) * NPTS];

    for (int n = t; n < NPTS; n += 256) cache[n] = fmaf(row[n], sc, sh);
    __syncthreads();

    float lastV = -3.402823466e38f;
    int   lastI = -1;

    for (int p = 0; p < 16; p++) {
        float bv = 3.402823466e38f;
        int   bi = NPTS;
        for (int n = t; n < NPTS; n += 256) {
            float val = cache[n];
            bool elig = (val > lastV) || (val == lastV && n > lastI);
            if (elig && (val < bv || (val == bv && n < bi))) { bv = val; bi = n; }
        }
        sVal[t] = bv; sIdx[t] = bi;
        __syncthreads();
        for (int st = 128; st > 0; st >>= 1) {
            if (t < st) {
                float ov = sVal[t + st]; int oi = sIdx[t + st];
                if (ov < sVal[t] || (ov == sVal[t] && oi < sIdx[t])) { sVal[t] = ov; sIdx[t] = oi; }
            }
            __syncthreads();
        }
        lastV = sVal[0]; lastI = sIdx[0];
        if (t == 0) selIdx[p] = sIdx[0];
        __syncthreads();
    }

    float part = 0.f;
    for (int i = t; i < 512; i += 256) {
        int c = i >> 4, p = i & 15;
        int n = selIdx[p];
        float val = fmaf(g_y3[((size_t)b * 32 + c) * NPTS + n], g_scale[2][c], g_shift[2][c]);
        part = fmaf(w9[c * 16 + p], val, part);
    }
    sVal[t] = part;
    __syncthreads();
    for (int st = 128; st > 0; st >>= 1) {
        if (t < st) sVal[t] += sVal[t + st];
        __syncthreads();
    }
    if (t == 0) g_v[b * 32 + k] = sVal[0] + b9[0];
}

// ---------------- fold glob into conv4 bias ---------------------------------
__global__ void bias4_kernel(const float* __restrict__ w4, const float* __restrict__ b4)
{
    int idx = blockIdx.x * 256 + threadIdx.x;
    if (idx >= BATCH * 512) return;
    int b = idx >> 9, co = idx & 511;
    float s = b4[co];
#pragma unroll
    for (int k = 0; k < 32; k++) s = fmaf(w4[co * 96 + k], g_v[b * 32 + k], s);
    g_bias4[idx] = s;
}

// ---------------------------------------------------------------------------
extern "C" void kernel_launch(void* const* d_in, const int* in_sizes, int n_in,
                              void* d_out, int out_size)
{
    const float* x   = (const float*)d_in[0];
    const float* w1  = (const float*)d_in[1];  const float* b1  = (const float*)d_in[2];
    const float* g1  = (const float*)d_in[3];  const float* be1 = (const float*)d_in[4];
    const float* w2  = (const float*)d_in[5];  const float* b2  = (const float*)d_in[6];
    const float* g2  = (const float*)d_in[7];  const float* be2 = (const float*)d_in[8];
    const float* w3  = (const float*)d_in[9];  const float* b3  = (const float*)d_in[10];
    const float* g3  = (const float*)d_in[11]; const float* be3 = (const float*)d_in[12];
    const float* w9  = (const float*)d_in[13]; const float* b9  = (const float*)d_in[14];
    const float* w4  = (const float*)d_in[15]; const float* b4  = (const float*)d_in[16];
    const float* g4  = (const float*)d_in[17]; const float* be4 = (const float*)d_in[18];
    const float* w5  = (const float*)d_in[19]; const float* b5  = (const float*)d_in[20];
    const float* g5  = (const float*)d_in[21]; const float* be5 = (const float*)d_in[22];
    const float* w6  = (const float*)d_in[23]; const float* b6  = (const float*)d_in[24];
    const float* g6  = (const float*)d_in[25]; const float* be6 = (const float*)d_in[26];
    const float* w7  = (const float*)d_in[27]; const float* b7  = (const float*)d_in[28];

    float *y1, *y2, *y3, *y6, *bias4p;
    __half *y4h, *y5h;
    cudaGetSymbolAddress((void**)&y1, g_y1);
    cudaGetSymbolAddress((void**)&y2, g_y2);
    cudaGetSymbolAddress((void**)&y3, g_y3);
    cudaGetSymbolAddress((void**)&y4h, g_y4h);
    cudaGetSymbolAddress((void**)&y5h, g_y5h);
    cudaGetSymbolAddress((void**)&y6, g_y6);
    cudaGetSymbolAddress((void**)&bias4p, g_bias4);

    const int SMEM3 = 2 * SBUF3_W * 4;   // 53248 B
    const int SMEM2 = 2 * SBUF2_W * 4;   // 35840 B
    cudaFuncSetAttribute(hmma_gemm_kernel<3,false,false>, cudaFuncAttributeMaxDynamicSharedMemorySize, SMEM3);
    cudaFuncSetAttribute(hmma_gemm_kernel<2,false,true>,  cudaFuncAttributeMaxDynamicSharedMemorySize, SMEM2);
    cudaFuncSetAttribute(hmma_gemm_kernel<1,true,true>,   cudaFuncAttributeMaxDynamicSharedMemorySize, SMEM2);
    cudaFuncSetAttribute(hmma_gemm_kernel<2,true,false>,  cudaFuncAttributeMaxDynamicSharedMemorySize, SMEM2);
    const int SPSM = NPTS * 4;           // 65536 B
    cudaFuncSetAttribute(softpool_kernel, cudaFuncAttributeMaxDynamicSharedMemorySize, SPSM);

    const dim3 blk(256);

    // L1: 4 -> 64 (fp32, fused stats)
    gemm_kernel<<<dim3(1, NTILE), blk>>>(w1, 4, b1, x, 4, y1, 64);
    finalize_kernel<<<64, 256>>>(g1, be1, 0);

    // L2: 64 -> 128 (3-term: feeds softpool selection)
    hmma_gemm_kernel<3,false,false><<<dim3(2, 2048), blk, SMEM3>>>(w2, 64, b2, 0, y1, 64, 0, y2, 128);
    finalize3_kernel<<<128, 256>>>(g2, be2, 1);

    // L3: 128 -> 32 (3-term: feeds softpool selection)
    hmma_gemm_kernel<3,false,false><<<dim3(1, 2048), blk, SMEM3>>>(w3, 128, b3, 0, y2, 128, 1, y3, 32);
    finalize3_kernel<<<32, 256>>>(g3, be3, 2);

    // SoftPool + fold glob into conv4 bias
    softpool_kernel<<<512, 256, SPSM>>>(w9, b9);
    bias4_kernel<<<32, 256>>>(w4, b4);

    // L4: 64 -> 512 (2-term, fp16 output)
    hmma_gemm_kernel<2,false,true><<<dim3(8, 2048), blk, SMEM2>>>(w4 + 32, 96, bias4p, 1, y1, 64, 0, y4h, 512);
    finalize3_kernel<<<512, 256>>>(g4, be4, 3);

    // L5: 512 -> 256 (1-term, fp16 in + out; 63% of MACs, smooth path)
    hmma_gemm_kernel<1,true,true><<<dim3(4, 2048), blk, SMEM2>>>(w5, 512, b5, 0, y4h, 512, 3, y5h, 256);
    finalize3_kernel<<<256, 256>>>(g5, be5, 4);

    // L6: 256 -> 128 (2-term, fp16 input, fp32 output for conv7)
    hmma_gemm_kernel<2,true,false><<<dim3(2, 2048), blk, SMEM2>>>(w6, 256, b6, 0, y5h, 256, 4, y6, 128);
    finalize3_kernel<<<128, 256>>>(g6, be6, 5);

    // L7: 128 -> 3, tanh, dedicated kernel, straight to output
    conv7_kernel<<<BNTOT/4/256, blk>>>(w7, b7, y6, (float*)d_out);
}

// round 16
// speedup vs baseline: 1.3795x; 1.0756x over previous
#include <cuda_runtime.h>
#include <cuda_fp16.h>
#include <math.h>
#include <stdint.h>

#define BATCH 16
#define NPTS  16384
#define BNTOT (BATCH*NPTS)
#define NTILE (BNTOT/256)   // 1024 column tiles (fp32 gemm path)
#define HPT   2048          // hmma stats partials per channel (1 per block)

typedef unsigned long long ull;

// ---------------- packed f32x2 / fp16 helpers --------------------------------
__device__ __forceinline__ ull pack2(float lo, float hi) {
    ull r; asm("mov.b64 %0, {%1, %2};" : "=l"(r) : "f"(lo), "f"(hi)); return r;
}
__device__ __forceinline__ ull fma2(ull a, ull b, ull c) {
    ull d; asm("fma.rn.f32x2 %0, %1, %2, %3;" : "=l"(d) : "l"(a), "l"(b), "l"(c)); return d;
}
__device__ __forceinline__ void unpack2(ull v, float& lo, float& hi) {
    asm("mov.b64 {%0, %1}, %2;" : "=f"(lo), "=f"(hi) : "l"(v));
}
__device__ __forceinline__ uint32_t cvt_h2(float lo, float hi) {
    uint32_t r;
    asm("cvt.rn.satfinite.f16x2.f32 %0, %1, %2;" : "=r"(r) : "f"(hi), "f"(lo));
    return r;
}
__device__ __forceinline__ float lo_h2(uint32_t h) {
    __half2 hh = *reinterpret_cast<const __half2*>(&h);
    return __low2float(hh);
}
__device__ __forceinline__ float hi_h2(uint32_t h) {
    __half2 hh = *reinterpret_cast<const __half2*>(&h);
    return __high2float(hh);
}
__device__ __forceinline__ void mma_f16(float d[4], const uint32_t a[4], const uint32_t b[2]) {
    asm volatile("mma.sync.aligned.m16n8k16.row.col.f32.f16.f16.f32 "
        "{%0,%1,%2,%3}, {%4,%5,%6,%7}, {%8,%9}, {%0,%1,%2,%3};"
        : "+f"(d[0]), "+f"(d[1]), "+f"(d[2]), "+f"(d[3])
        : "r"(a[0]), "r"(a[1]), "r"(a[2]), "r"(a[3]), "r"(b[0]), "r"(b[1]));
}
// canonical A-fragment load: 16x16 f16 tile, rows contiguous in smem
__device__ __forceinline__ void ldsm_x4(uint32_t r[4], const uint32_t* p) {
    uint32_t a = (uint32_t)__cvta_generic_to_shared(p);
    asm volatile("ldmatrix.sync.aligned.m8n8.x4.shared.b16 {%0,%1,%2,%3}, [%4];"
        : "=r"(r[0]), "=r"(r[1]), "=r"(r[2]), "=r"(r[3]) : "r"(a));
}

// ---------------- scratch (device globals) ----------------------------------
__device__ float  g_y1[(size_t)BATCH*64*NPTS];
__device__ float  g_y2[(size_t)BATCH*128*NPTS];
__device__ float  g_y3[(size_t)BATCH*32*NPTS];
__device__ __half g_y4h[(size_t)BATCH*512*NPTS];   // fp16 activations (smooth path)
__device__ __half g_y5h[(size_t)BATCH*256*NPTS];
__device__ float  g_y6[(size_t)BATCH*128*NPTS];
__device__ float g_bsum[(size_t)64*NTILE];      // L1 fused stats [c][tile]
__device__ float g_bsq [(size_t)64*NTILE];
__device__ float g_hsum[(size_t)512*HPT];       // hmma fused stats [c][blockIdx.y]
__device__ float g_hsq [(size_t)512*HPT];
__device__ float g_scale[6][512];
__device__ float g_shift[6][512];
__device__ float g_v[BATCH*32];
__device__ float g_bias4[BATCH*512];

// =================== HMMA fp16 split GEMM (layers 2-6) =======================
// TERMS=3: A=[wh|wl], B=[xh|xl]; D = wh*xh + wh*xl + wl*xh  (~2e-6)
// TERMS=2: A=[wh|wl], B=x16;     D = wh*x + wl*x            (~3e-4/layer)
// TERMS=1: A=wh,      B=x16;     D = w16*x16                (~4.2e-4/layer)
// INF16 : X is fp16; OUTF16: Y stored fp16.
// KG    : k16 groups per chunk (2 -> 32ch, 4 -> 64ch; KG=4 only for TERMS=1).
// Epilogue reduces stats partials across warpN in smem -> 1 partial/block.
#define A_STR 36                 // 32 data words + 4 pad
#define B_STR 136                // 128 data words + 8 pad
#define B0_W  2304               // A region = 64*36 words

template<int TERMS, bool INF16, bool OUTF16, int KG>
__global__ void __launch_bounds__(256, 2)
hmma_gemm_kernel(const float* __restrict__ W, int wstride,
                 const float* __restrict__ bias, int biasPerBatch,
                 const void* __restrict__ Xv, int Ci, int inLayer,
                 void* __restrict__ Yv, int Co)
{
    extern __shared__ uint32_t sm[];
    constexpr int BROWS  = (TERMS == 3) ? 32 : KG*8;      // B k-pair rows
    constexpr int SBUF_W = B0_W + BROWS * B_STR;
    constexpr int RED0   = 2 * SBUF_W;                    // stats reduction pad
    const int t    = threadIdx.x;
    const int lane = t & 31, wid = t >> 5;
    const int warpM = wid & 1, warpN = wid >> 1;   // 2 x 4 warps, warp tile 32x32
    const int l4 = lane >> 2, q = lane & 3;
    const int b   = blockIdx.y >> 7;
    const int n0  = (blockIdx.y & 127) * 128;
    const int co0 = blockIdx.x * 64;

    const float*  __restrict__ Xf = (const float*)Xv;
    const __half* __restrict__ Xh = (const __half*)Xv;
    float*  __restrict__ Yf = (float*)Yv;
    __half* __restrict__ Yh = (__half*)Yv;

    const float* __restrict__ scv = g_scale[inLayer];
    const float* __restrict__ shv = g_shift[inLayer];
    const int nChunks = Ci / (KG * 16);

    float acc[2][4][4];
#pragma unroll
    for (int mt = 0; mt < 2; mt++)
#pragma unroll
        for (int nt = 0; nt < 4; nt++)
#pragma unroll
            for (int j = 0; j < 4; j++) acc[mt][nt][j] = 0.f;

    // register staging for the in-flight chunk
    float4 aw[KG];                // weights (KG*4 floats per thread)
    float4 bx0[2], bx1[2];        // activations fp32 path (KG=2 only)
    uint4  beH[KG/2], boH[KG/2];  // activations fp16 path

    auto ldg_chunk = [&](int ci0) {
#pragma unroll
        for (int i = 0; i < KG; i++) {
            int slot = i*256 + t;
            int co = (KG == 2) ? (slot >> 3) : (slot >> 4);
            int f4 = (KG == 2) ? (slot & 7)  : (slot & 15);
            int cog = co0 + co;
            aw[i] = (cog < Co) ? *(const float4*)&W[(size_t)cog*wstride + ci0 + f4*4]
                               : make_float4(0.f, 0.f, 0.f, 0.f);
        }
        if (INF16) {
#pragma unroll
            for (int i = 0; i < KG/2; i++) {
                int slot = i*256 + t;
                int kp = slot >> 4, f8 = slot & 15;
                int c0 = ci0 + kp*2;
                beH[i] = *(const uint4*)&Xh[((size_t)b*Ci + c0  )*NPTS + n0 + f8*8];
                boH[i] = *(const uint4*)&Xh[((size_t)b*Ci + c0+1)*NPTS + n0 + f8*8];
            }
        } else {
#pragma unroll
            for (int i = 0; i < 2; i++) {
                int slot = i*256 + t;
                int kp = slot >> 5, f4 = slot & 31;
                int c0 = ci0 + kp*2;
                bx0[i] = *(const float4*)&Xf[((size_t)b*Ci + c0  )*NPTS + n0 + f4*4];
                bx1[i] = *(const float4*)&Xf[((size_t)b*Ci + c0+1)*NPTS + n0 + f4*4];
            }
        }
    };

    auto sts_chunk = [&](int bufW, int ci0) {
        // A: wh always; wl when TERMS >= 2
#pragma unroll
        for (int i = 0; i < KG; i++) {
            int slot = i*256 + t;
            int co = (KG == 2) ? (slot >> 3) : (slot >> 4);
            int f4 = (KG == 2) ? (slot & 7)  : (slot & 15);
            float4 w = aw[i];
            uint32_t h0 = cvt_h2(w.x, w.y);
            uint32_t h1 = cvt_h2(w.z, w.w);
            int wi = bufW + co*A_STR + f4*2;
            *(uint2*)&sm[wi] = make_uint2(h0, h1);        // wh
            if (TERMS >= 2) {
                uint32_t l0 = cvt_h2(w.x - lo_h2(h0), w.y - hi_h2(h0));
                uint32_t l1 = cvt_h2(w.z - lo_h2(h1), w.w - hi_h2(h1));
                *(uint2*)&sm[wi + 16] = make_uint2(l0, l1);   // wl
            }
        }
        // B staging, BN+ReLU fused
        if (INF16) {
#pragma unroll
            for (int i = 0; i < KG/2; i++) {
                int slot = i*256 + t;
                int kp = slot >> 4, f8 = slot & 15;
                int c0 = ci0 + kp*2;
                float s0 = scv[c0],   h0s = shv[c0];
                float s1 = scv[c0+1], h1s = shv[c0+1];
                const uint32_t* ew = (const uint32_t*)&beH[i];
                const uint32_t* ow = (const uint32_t*)&boH[i];
                uint32_t pk[8];
#pragma unroll
                for (int j = 0; j < 4; j++) {
                    float e0 = fmaxf(fmaf(lo_h2(ew[j]), s0, h0s), 0.f);
                    float e1 = fmaxf(fmaf(hi_h2(ew[j]), s0, h0s), 0.f);
                    float o0 = fmaxf(fmaf(lo_h2(ow[j]), s1, h1s), 0.f);
                    float o1 = fmaxf(fmaf(hi_h2(ow[j]), s1, h1s), 0.f);
                    pk[j*2+0] = cvt_h2(e0, o0);
                    pk[j*2+1] = cvt_h2(e1, o1);
                }
                int wi = bufW + B0_W + kp*B_STR + f8*8;
                *(uint4*)&sm[wi]     = make_uint4(pk[0], pk[1], pk[2], pk[3]);
                *(uint4*)&sm[wi + 4] = make_uint4(pk[4], pk[5], pk[6], pk[7]);
            }
        } else {
#pragma unroll
            for (int i = 0; i < 2; i++) {
                int slot = i*256 + t;
                int kp = slot >> 5, f4 = slot & 31;
                int c0 = ci0 + kp*2;
                float s0 = scv[c0],   h0s = shv[c0];
                float s1 = scv[c0+1], h1s = shv[c0+1];
                float x0[4] = {bx0[i].x, bx0[i].y, bx0[i].z, bx0[i].w};
                float x1[4] = {bx1[i].x, bx1[i].y, bx1[i].z, bx1[i].w};
                uint32_t hw[4], lw[4];
#pragma unroll
                for (int j = 0; j < 4; j++) {
                    float a0 = fmaxf(fmaf(x0[j], s0, h0s), 0.f);
                    float a1 = fmaxf(fmaf(x1[j], s1, h1s), 0.f);
                    uint32_t h = cvt_h2(a0, a1);
                    hw[j] = h;
                    if (TERMS == 3) lw[j] = cvt_h2(a0 - lo_h2(h), a1 - hi_h2(h));
                }
                int wi = bufW + B0_W + kp*B_STR + f4*4;
                *(uint4*)&sm[wi] = make_uint4(hw[0], hw[1], hw[2], hw[3]);            // xh / x16
                if (TERMS == 3)
                    *(uint4*)&sm[wi + 16*B_STR] = make_uint4(lw[0], lw[1], lw[2], lw[3]); // xl
            }
        }
    };

    ldg_chunk(0);   // prologue

    // ldmatrix addressing (constant per thread)
    const int lrow = lane & 15;
    const int lkw  = (lane >> 4) * 4;

    for (int c = 0; c < nChunks; c++) {
        const int bufW = (c & 1) * SBUF_W;
        sts_chunk(bufW, c * KG * 16);
        __syncthreads();                         // STS(c) visible to all warps
        if (c + 1 < nChunks) ldg_chunk((c+1) * KG * 16);   // latency hidden by compute

        const uint32_t* Aw = sm + bufW;
        const uint32_t* Bx = sm + bufW + B0_W;

#pragma unroll
        for (int kg = 0; kg < KG; kg++) {        // k16 group within the chunk
            uint32_t ah[2][4], al[2][4];
#pragma unroll
            for (int mt = 0; mt < 2; mt++) {
                const uint32_t* base =
                    Aw + (warpM*32 + mt*16 + lrow) * A_STR + kg*8 + lkw;
                ldsm_x4(ah[mt], base);           // wh fragment
                if (TERMS >= 2) ldsm_x4(al[mt], base + 16);   // wl fragment
            }
            uint32_t bh[4][2], bl[4][2];
#pragma unroll
            for (int nt = 0; nt < 4; nt++) {
                int base = (kg*8 + q) * B_STR + warpN*32 + nt*8 + l4;
                bh[nt][0] = Bx[base];             bh[nt][1] = Bx[base + 4*B_STR];
                if (TERMS == 3) {
                    bl[nt][0] = Bx[base + 16*B_STR];  bl[nt][1] = Bx[base + 20*B_STR];
                }
            }
#pragma unroll
            for (int mt = 0; mt < 2; mt++)
#pragma unroll
                for (int nt = 0; nt < 4; nt++) {
                    mma_f16(acc[mt][nt], ah[mt], bh[nt]);             // wh * x
                    if (TERMS == 3) {
                        mma_f16(acc[mt][nt], ah[mt], bl[nt]);         // wh * xl
                        mma_f16(acc[mt][nt], al[mt], bh[nt]);         // wl * xh
                    } else if (TERMS == 2) {
                        mma_f16(acc[mt][nt], al[mt], bh[nt]);         // wl * x
                    }
                }
        }
    }

    // ---- epilogue: store Y + cross-warpN-reduced stats partials ----
    float* redS = (float*)(sm + RED0);        // [warpN][64 rows]
    float* redQ = (float*)(sm + RED0 + 256);
#pragma unroll
    for (int mt = 0; mt < 2; mt++) {
        int row0 = co0 + warpM*32 + mt*16 + l4;
        int row1 = row0 + 8;
        float bs0 = 0.f, bs1 = 0.f;
        if (row0 < Co) bs0 = biasPerBatch ? bias[(size_t)b*Co + row0] : bias[row0];
        if (row1 < Co) bs1 = biasPerBatch ? bias[(size_t)b*Co + row1] : bias[row1];
        float s0 = 0.f, q0 = 0.f, s1 = 0.f, q1 = 0.f;
#pragma unroll
        for (int nt = 0; nt < 4; nt++) {
            int col = n0 + warpN*32 + nt*8 + q*2;
            float o0 = acc[mt][nt][0] + bs0, o1 = acc[mt][nt][1] + bs0;
            float o2 = acc[mt][nt][2] + bs1, o3 = acc[mt][nt][3] + bs1;
            s0 += o0 + o1;  q0 = fmaf(o0, o0, q0); q0 = fmaf(o1, o1, q0);
            s1 += o2 + o3;  q1 = fmaf(o2, o2, q1); q1 = fmaf(o3, o3, q1);
            if (OUTF16) {
                if (row0 < Co)
                    *(uint32_t*)&Yh[((size_t)b*Co + row0)*NPTS + col] = cvt_h2(o0, o1);
                if (row1 < Co)
                    *(uint32_t*)&Yh[((size_t)b*Co + row1)*NPTS + col] = cvt_h2(o2, o3);
            } else {
                if (row0 < Co)
                    *(float2*)&Yf[((size_t)b*Co + row0)*NPTS + col] = make_float2(o0, o1);
                if (row1 < Co)
                    *(float2*)&Yf[((size_t)b*Co + row1)*NPTS + col] = make_float2(o2, o3);
            }
        }
        s0 += __shfl_xor_sync(0xffffffffu, s0, 1);  s0 += __shfl_xor_sync(0xffffffffu, s0, 2);
        q0 += __shfl_xor_sync(0xffffffffu, q0, 1);  q0 += __shfl_xor_sync(0xffffffffu, q0, 2);
        s1 += __shfl_xor_sync(0xffffffffu, s1, 1);  s1 += __shfl_xor_sync(0xffffffffu, s1, 2);
        q1 += __shfl_xor_sync(0xffffffffu, q1, 1);  q1 += __shfl_xor_sync(0xffffffffu, q1, 2);
        if (q == 0) {
            int r0 = warpM*32 + mt*16 + l4;
            redS[warpN*64 + r0]     = s0;  redQ[warpN*64 + r0]     = q0;
            redS[warpN*64 + r0 + 8] = s1;  redQ[warpN*64 + r0 + 8] = q1;
        }
    }
    __syncthreads();
    if (t < 64) {
        float s = redS[t] + redS[64 + t] + redS[128 + t] + redS[192 + t];
        float qv = redQ[t] + redQ[64 + t] + redQ[128 + t] + redQ[192 + t];
        int cog = co0 + t;
        if (cog < Co) {
            g_hsum[(size_t)cog*HPT + blockIdx.y] = s;
            g_hsq [(size_t)cog*HPT + blockIdx.y] = qv;
        }
    }
}

// ---------------- finalize3: reduce HPT partials -> BN scale/shift ----------
__global__ void __launch_bounds__(256)
finalize3_kernel(const float* __restrict__ gamma,
                 const float* __restrict__ beta, int layer)
{
    const int c = blockIdx.x;
    const int t = threadIdx.x;
    float s = 0.f, q = 0.f;
#pragma unroll
    for (int i = 0; i < HPT/256; i++) {
        s += g_hsum[(size_t)c * HPT + i*256 + t];
        q += g_hsq [(size_t)c * HPT + i*256 + t];
    }
    __shared__ float ss[256], sq[256];
    ss[t] = s; sq[t] = q;
    __syncthreads();
    for (int st = 128; st > 0; st >>= 1) {
        if (t < st) { ss[t] += ss[t + st]; sq[t] += sq[t + st]; }
        __syncthreads();
    }
    if (t == 0) {
        float m   = ss[0] * (1.0f / BNTOT);
        float var = sq[0] * (1.0f / BNTOT) - m * m;
        float rstd = rsqrtf(var + 1e-5f);
        float scl  = gamma[c] * rstd;
        g_scale[layer][c] = scl;
        g_shift[layer][c] = fmaf(-m, scl, beta[c]);
    }
}

// =================== fp32 FFMA2 GEMM (layer 1 only) ==========================
__global__ void __launch_bounds__(256, 2)
gemm_kernel(const float* __restrict__ W, int wstride,
            const float* __restrict__ bias,
            const float* __restrict__ X, int Ci,
            float* __restrict__ Y, int Co)
{
    __shared__ __align__(16) ull   As2[16][65];
    __shared__ __align__(16) float Xs[16][256];

    const int t  = threadIdx.x;
    const int tn = t & 15;
    const int r  = t >> 4;
    const int tilesPerBatch = NPTS / 256;
    const int b   = blockIdx.y / tilesPerBatch;
    const int n0  = (blockIdx.y % tilesPerBatch) * 256;
    const int co0 = blockIdx.x * 64;

    ull acc2[4][8];
#pragma unroll
    for (int j = 0; j < 4; j++)
#pragma unroll
        for (int qq = 0; qq < 8; qq++) acc2[j][qq] = 0ull;

    const int nChunks = (Ci + 15) >> 4;
    float  wreg[4];
    float4 xreg[4];

    {
#pragma unroll
        for (int i = 0; i < 4; i++) {
            int lin = i*256 + t;
            int k = lin & 15, co = lin >> 4;
            int ci = k, cog = co0 + co;
            wreg[i] = (ci < Ci && cog < Co) ? W[(size_t)cog * wstride + ci] : 0.f;
        }
#pragma unroll
        for (int i = 0; i < 4; i++) {
            int fidx = i*256 + t;
            int k  = fidx >> 6;
            int n4 = fidx & 63;
            xreg[i] = (k < Ci) ? *(const float4*)&X[((size_t)b * Ci + k) * NPTS + n0 + n4*4]
                               : make_float4(0.f,0.f,0.f,0.f);
        }
    }

    for (int c = 0; c < nChunks; c++) {
        const int k0 = c << 4;
        if (c > 0) __syncthreads();
#pragma unroll
        for (int i = 0; i < 4; i++) {
            int lin = i*256 + t;
            int k = lin & 15, co = lin >> 4;
            float w = wreg[i];
            As2[k][co] = pack2(w, w);
        }
#pragma unroll
        for (int i = 0; i < 4; i++) {
            int fidx = i*256 + t;
            int k  = fidx >> 6;
            int n4 = fidx & 63;
            *(float4*)&Xs[k][n4*4] = xreg[i];
        }
        __syncthreads();

        if (c + 1 < nChunks) {
            const int k0n = k0 + 16;
#pragma unroll
            for (int i = 0; i < 4; i++) {
                int lin = i*256 + t;
                int k = lin & 15, co = lin >> 4;
                int ci = k0n + k, cog = co0 + co;
                wreg[i] = (ci < Ci && cog < Co) ? W[(size_t)cog * wstride + ci] : 0.f;
            }
#pragma unroll
            for (int i = 0; i < 4; i++) {
                int fidx = i*256 + t;
                int k  = fidx >> 6;
                int n4 = fidx & 63;
                int ci = k0n + k;
                xreg[i] = (ci < Ci) ? *(const float4*)&X[((size_t)b * Ci + ci) * NPTS + n0 + n4*4]
                                    : make_float4(0.f,0.f,0.f,0.f);
            }
        }

#pragma unroll
        for (int kk = 0; kk < 16; kk++) {
            ull a0 = As2[kk][r*4 + 0];
            ull a1 = As2[kk][r*4 + 1];
            ull a2 = As2[kk][r*4 + 2];
            ull a3 = As2[kk][r*4 + 3];
#pragma unroll
            for (int g = 0; g < 4; g++) {
                ulonglong2 xv = *(const ulonglong2*)&Xs[kk][g*64 + tn*4];
                acc2[0][g*2+0] = fma2(a0, xv.x, acc2[0][g*2+0]);
                acc2[0][g*2+1] = fma2(a0, xv.y, acc2[0][g*2+1]);
                acc2[1][g*2+0] = fma2(a1, xv.x, acc2[1][g*2+0]);
                acc2[1][g*2+1] = fma2(a1, xv.y, acc2[1][g*2+1]);
                acc2[2][g*2+0] = fma2(a2, xv.x, acc2[2][g*2+0]);
                acc2[2][g*2+1] = fma2(a2, xv.y, acc2[2][g*2+1]);
                acc2[3][g*2+0] = fma2(a3, xv.x, acc2[3][g*2+0]);
                acc2[3][g*2+1] = fma2(a3, xv.y, acc2[3][g*2+1]);
            }
        }
    }

    const int tile = blockIdx.y;
#pragma unroll
    for (int j = 0; j < 4; j++) {
        int cog = co0 + r*4 + j;
        bool valid = (cog < Co);
        float bs = valid ? bias[cog] : 0.f;
        float s = 0.f, q = 0.f;
        float* yr = valid ? &Y[((size_t)b * Co + cog) * NPTS + n0] : (float*)0;
#pragma unroll
        for (int g = 0; g < 4; g++) {
            float4 o;
            unpack2(acc2[j][g*2+0], o.x, o.y);
            unpack2(acc2[j][g*2+1], o.z, o.w);
            o.x += bs; o.y += bs; o.z += bs; o.w += bs;
            s += (o.x + o.y) + (o.z + o.w);
            q = fmaf(o.x, o.x, q); q = fmaf(o.y, o.y, q);
            q = fmaf(o.z, o.z, q); q = fmaf(o.w, o.w, q);
            if (valid) *(float4*)&yr[g*64 + tn*4] = o;
        }
#pragma unroll
        for (int off = 8; off; off >>= 1) {
            s += __shfl_down_sync(0xffffffffu, s, off, 16);
            q += __shfl_down_sync(0xffffffffu, q, off, 16);
        }
        if (tn == 0 && valid) {
            g_bsum[(size_t)cog * NTILE + tile] = s;
            g_bsq [(size_t)cog * NTILE + tile] = q;
        }
    }
}

// ---------------- finalize for L1 ([c][NTILE]) -------------------------------
__global__ void __launch_bounds__(256)
finalize_kernel(const float* __restrict__ gamma,
                const float* __restrict__ beta, int layer)
{
    const int c = blockIdx.x;
    const int t = threadIdx.x;
    float s = 0.f, q = 0.f;
#pragma unroll
    for (int i = 0; i < NTILE/256; i++) {
        s += g_bsum[(size_t)c * NTILE + i*256 + t];
        q += g_bsq [(size_t)c * NTILE + i*256 + t];
    }
    __shared__ float ss[256], sq[256];
    ss[t] = s; sq[t] = q;
    __syncthreads();
    for (int st = 128; st > 0; st >>= 1) {
        if (t < st) { ss[t] += ss[t + st]; sq[t] += sq[t + st]; }
        __syncthreads();
    }
    if (t == 0) {
        float m   = ss[0] * (1.0f / BNTOT);
        float var = sq[0] * (1.0f / BNTOT) - m * m;
        float rstd = rsqrtf(var + 1e-5f);
        float scl  = gamma[c] * rstd;
        g_scale[layer][c] = scl;
        g_shift[layer][c] = fmaf(-m, scl, beta[c]);
    }
}

// ---------------- dedicated L7: 128 -> 3, tanh ------------------------------
__global__ void __launch_bounds__(256)
conv7_kernel(const float* __restrict__ w7, const float* __restrict__ b7,
             const float* __restrict__ Y6, float* __restrict__ out)
{
    __shared__ float sw0[128], sw1[128], sw2[128], ssc[128], ssh[128];
    const int t = threadIdx.x;
    if (t < 128) {
        sw0[t] = w7[t]; sw1[t] = w7[128 + t]; sw2[t] = w7[256 + t];
        ssc[t] = g_scale[5][t]; ssh[t] = g_shift[5][t];
    }
    __syncthreads();

    const int idx = blockIdx.x * 256 + t;        // 65536 threads, 4 pts each
    const int b = idx >> 12;
    const int n = (idx & 4095) * 4;

    float4 a0 = make_float4(0.f,0.f,0.f,0.f);
    float4 a1 = a0, a2 = a0;
#pragma unroll 4
    for (int c = 0; c < 128; c++) {
        float4 v = *(const float4*)&Y6[((size_t)b*128 + c)*NPTS + n];
        float s = ssc[c], h = ssh[c];
        v.x = fmaxf(fmaf(v.x, s, h), 0.f);
        v.y = fmaxf(fmaf(v.y, s, h), 0.f);
        v.z = fmaxf(fmaf(v.z, s, h), 0.f);
        v.w = fmaxf(fmaf(v.w, s, h), 0.f);
        float w0 = sw0[c], w1 = sw1[c], w2 = sw2[c];
        a0.x = fmaf(w0, v.x, a0.x); a0.y = fmaf(w0, v.y, a0.y);
        a0.z = fmaf(w0, v.z, a0.z); a0.w = fmaf(w0, v.w, a0.w);
        a1.x = fmaf(w1, v.x, a1.x); a1.y = fmaf(w1, v.y, a1.y);
        a1.z = fmaf(w1, v.z, a1.z); a1.w = fmaf(w1, v.w, a1.w);
        a2.x = fmaf(w2, v.x, a2.x); a2.y = fmaf(w2, v.y, a2.y);
        a2.z = fmaf(w2, v.z, a2.z); a2.w = fmaf(w2, v.w, a2.w);
    }
    float b0 = b7[0], b1 = b7[1], b2 = b7[2];
    float4 o0 = make_float4(tanhf(a0.x+b0), tanhf(a0.y+b0), tanhf(a0.z+b0), tanhf(a0.w+b0));
    float4 o1 = make_float4(tanhf(a1.x+b1), tanhf(a1.y+b1), tanhf(a1.z+b1), tanhf(a1.w+b1));
    float4 o2 = make_float4(tanhf(a2.x+b2), tanhf(a2.y+b2), tanhf(a2.z+b2), tanhf(a2.w+b2));
    *(float4*)&out[((size_t)b*3 + 0)*NPTS + n] = o0;
    *(float4*)&out[((size_t)b*3 + 1)*NPTS + n] = o1;
    *(float4*)&out[((size_t)b*3 + 2)*NPTS + n] = o2;
}

// ---------------- SoftPool with smem row cache -------------------------------
__global__ void __launch_bounds__(256)
softpool_kernel(const float* __restrict__ w9, const float* __restrict__ b9)
{
    extern __shared__ float cache[];   // 16384 floats (64 KB)
    const int b = blockIdx.x >> 5;
    const int k = blockIdx.x & 31;
    const int t = threadIdx.x;

    __shared__ float sVal[256];
    __shared__ int   sIdx[256];
    __shared__ int   selIdx[16];

    const float sc = g_scale[2][k], sh = g_shift[2][k];
    const float* __restrict__ row = &g_y3[((size_t)b * 32 + k) * NPTS];

    for (int n = t; n < NPTS; n += 256) cache[n] = fmaf(row[n], sc, sh);
    __syncthreads();

    float lastV = -3.402823466e38f;
    int   lastI = -1;

    for (int p = 0; p < 16; p++) {
        float bv = 3.402823466e38f;
        int   bi = NPTS;
        for (int n = t; n < NPTS; n += 256) {
            float val = cache[n];
            bool elig = (val > lastV) || (val == lastV && n > lastI);
            if (elig && (val < bv || (val == bv && n < bi))) { bv = val; bi = n; }
        }
        sVal[t] = bv; sIdx[t] = bi;
        __syncthreads();
        for (int st = 128; st > 0; st >>= 1) {
            if (t < st) {
                float ov = sVal[t + st]; int oi = sIdx[t + st];
                if (ov < sVal[t] || (ov == sVal[t] && oi < sIdx[t])) { sVal[t] = ov; sIdx[t] = oi; }
            }
            __syncthreads();
        }
        lastV = sVal[0]; lastI = sIdx[0];
        if (t == 0) selIdx[p] = sIdx[0];
        __syncthreads();
    }

    float part = 0.f;
    for (int i = t; i < 512; i += 256) {
        int c = i >> 4, p = i & 15;
        int n = selIdx[p];
        float val = fmaf(g_y3[((size_t)b * 32 + c) * NPTS + n], g_scale[2][c], g_shift[2][c]);
        part = fmaf(w9[c * 16 + p], val, part);
    }
    sVal[t] = part;
    __syncthreads();
    for (int st = 128; st > 0; st >>= 1) {
        if (t < st) sVal[t] += sVal[t + st];
        __syncthreads();
    }
    if (t == 0) g_v[b * 32 + k] = sVal[0] + b9[0];
}

// ---------------- fold glob into conv4 bias ---------------------------------
__global__ void bias4_kernel(const float* __restrict__ w4, const float* __restrict__ b4)
{
    int idx = blockIdx.x * 256 + threadIdx.x;
    if (idx >= BATCH * 512) return;
    int b = idx >> 9, co = idx & 511;
    float s = b4[co];
#pragma unroll
    for (int k = 0; k < 32; k++) s = fmaf(w4[co * 96 + k], g_v[b * 32 + k], s);
    g_bias4[idx] = s;
}

// ---------------------------------------------------------------------------
extern "C" void kernel_launch(void* const* d_in, const int* in_sizes, int n_in,
                              void* d_out, int out_size)
{
    const float* x   = (const float*)d_in[0];
    const float* w1  = (const float*)d_in[1];  const float* b1  = (const float*)d_in[2];
    const float* g1  = (const float*)d_in[3];  const float* be1 = (const float*)d_in[4];
    const float* w2  = (const float*)d_in[5];  const float* b2  = (const float*)d_in[6];
    const float* g2  = (const float*)d_in[7];  const float* be2 = (const float*)d_in[8];
    const float* w3  = (const float*)d_in[9];  const float* b3  = (const float*)d_in[10];
    const float* g3  = (const float*)d_in[11]; const float* be3 = (const float*)d_in[12];
    const float* w9  = (const float*)d_in[13]; const float* b9  = (const float*)d_in[14];
    const float* w4  = (const float*)d_in[15]; const float* b4  = (const float*)d_in[16];
    const float* g4  = (const float*)d_in[17]; const float* be4 = (const float*)d_in[18];
    const float* w5  = (const float*)d_in[19]; const float* b5  = (const float*)d_in[20];
    const float* g5  = (const float*)d_in[21]; const float* be5 = (const float*)d_in[22];
    const float* w6  = (const float*)d_in[23]; const float* b6  = (const float*)d_in[24];
    const float* g6  = (const float*)d_in[25]; const float* be6 = (const float*)d_in[26];
    const float* w7  = (const float*)d_in[27]; const float* b7  = (const float*)d_in[28];

    float *y1, *y2, *y3, *y6, *bias4p;
    __half *y4h, *y5h;
    cudaGetSymbolAddress((void**)&y1, g_y1);
    cudaGetSymbolAddress((void**)&y2, g_y2);
    cudaGetSymbolAddress((void**)&y3, g_y3);
    cudaGetSymbolAddress((void**)&y4h, g_y4h);
    cudaGetSymbolAddress((void**)&y5h, g_y5h);
    cudaGetSymbolAddress((void**)&y6, g_y6);
    cudaGetSymbolAddress((void**)&bias4p, g_bias4);

    // smem sizes: 2 x SBUF + 2KB stats-reduction pad
    const int SM_T3 = 2 * (B0_W + 32*B_STR) * 4 + 2048;   // 55296
    const int SM_T2 = 2 * (B0_W + 16*B_STR) * 4 + 2048;   // 37888
    const int SM_T1 = 2 * (B0_W + 32*B_STR) * 4 + 2048;   // 55296 (KG=4)
    cudaFuncSetAttribute(hmma_gemm_kernel<3,false,false,2>, cudaFuncAttributeMaxDynamicSharedMemorySize, SM_T3);
    cudaFuncSetAttribute(hmma_gemm_kernel<2,false,true,2>,  cudaFuncAttributeMaxDynamicSharedMemorySize, SM_T2);
    cudaFuncSetAttribute(hmma_gemm_kernel<1,true,true,4>,   cudaFuncAttributeMaxDynamicSharedMemorySize, SM_T1);
    cudaFuncSetAttribute(hmma_gemm_kernel<2,true,false,2>,  cudaFuncAttributeMaxDynamicSharedMemorySize, SM_T2);
    const int SPSM = NPTS * 4;           // 65536 B
    cudaFuncSetAttribute(softpool_kernel, cudaFuncAttributeMaxDynamicSharedMemorySize, SPSM);

    const dim3 blk(256);

    // L1: 4 -> 64 (fp32, fused stats)
    gemm_kernel<<<dim3(1, NTILE), blk>>>(w1, 4, b1, x, 4, y1, 64);
    finalize_kernel<<<64, 256>>>(g1, be1, 0);

    // L2: 64 -> 128 (3-term: feeds softpool selection)
    hmma_gemm_kernel<3,false,false,2><<<dim3(2, 2048), blk, SM_T3>>>(w2, 64, b2, 0, y1, 64, 0, y2, 128);
    finalize3_kernel<<<128, 256>>>(g2, be2, 1);

    // L3: 128 -> 32 (3-term: feeds softpool selection)
    hmma_gemm_kernel<3,false,false,2><<<dim3(1, 2048), blk, SM_T3>>>(w3, 128, b3, 0, y2, 128, 1, y3, 32);
    finalize3_kernel<<<32, 256>>>(g3, be3, 2);

    // SoftPool + fold glob into conv4 bias
    softpool_kernel<<<512, 256, SPSM>>>(w9, b9);
    bias4_kernel<<<32, 256>>>(w4, b4);

    // L4: 64 -> 512 (2-term, fp16 output)
    hmma_gemm_kernel<2,false,true,2><<<dim3(8, 2048), blk, SM_T2>>>(w4 + 32, 96, bias4p, 1, y1, 64, 0, y4h, 512);
    finalize3_kernel<<<512, 256>>>(g4, be4, 3);

    // L5: 512 -> 256 (1-term, fp16 in+out, K-chunk 64)
    hmma_gemm_kernel<1,true,true,4><<<dim3(4, 2048), blk, SM_T1>>>(w5, 512, b5, 0, y4h, 512, 3, y5h, 256);
    finalize3_kernel<<<256, 256>>>(g5, be5, 4);

    // L6: 256 -> 128 (2-term, fp16 input, fp32 output for conv7)
    hmma_gemm_kernel<2,true,false,2><<<dim3(2, 2048), blk, SM_T2>>>(w6, 256, b6, 0, y5h, 256, 4, y6, 128);
    finalize3_kernel<<<128, 256>>>(g6, be6, 5);

    // L7: 128 -> 3, tanh, dedicated kernel, straight to output
    conv7_kernel<<<BNTOT/4/256, blk>>>(w7, b7, y6, (float*)d_out);
}